// round 1
// baseline (speedup 1.0000x reference)
#include <cuda_runtime.h>
#include <math.h>

#define B_ 2
#define S_ 1024
#define D_ 2048
#define H_ 16
#define HKV_ 8
#define HD_ 128
#define F_ 5632
#define E_ 8
#define R_ 16
#define T_ (B_*S_)
#define EPS_ 1e-5f
#define SCALE_ 2.0f

// ---------------- device scratch (static, allocation-free) ----------------
__device__ float g_xn[T_*D_];
__device__ float g_q[T_*D_];
__device__ float g_k[T_*HKV_*HD_];
__device__ float g_v[T_*HKV_*HD_];
__device__ float g_attn[T_*D_];
__device__ float g_sn[T_*D_];
__device__ float g_c1[T_*F_];
__device__ float g_c3[T_*F_];
__device__ float g_h1[T_*F_];   // reused as sr after silu
__device__ float g_h3[T_*F_];
__device__ float g_u1[T_*R_];
__device__ float g_u3[T_*R_];
__device__ float g_u2[T_*R_];
__device__ float g_logits[T_*E_];
__device__ float g_zmax[B_*E_];
__device__ float g_zsum[B_*E_];
__device__ int   g_cnt[E_];
__device__ int   g_tok[E_*T_];
__device__ float g_tw[E_*T_];

// ---------------- small kernels ----------------
__global__ void reset_kernel(int* cnt) {
    if (threadIdx.x < E_) cnt[threadIdx.x] = 0;
}

__global__ void rmsnorm_kernel(const float* __restrict__ x, const float* __restrict__ w,
                               float* __restrict__ out) {
    int row = blockIdx.x;
    const float* xr = x + (size_t)row * D_;
    float ss = 0.f;
    for (int i = threadIdx.x; i < D_; i += 256) { float v = xr[i]; ss += v * v; }
    __shared__ float red[256];
    red[threadIdx.x] = ss; __syncthreads();
    for (int s = 128; s > 0; s >>= 1) {
        if (threadIdx.x < s) red[threadIdx.x] += red[threadIdx.x + s];
        __syncthreads();
    }
    float inv = rsqrtf(red[0] / (float)D_ + EPS_);
    float* orow = out + (size_t)row * D_;
    for (int i = threadIdx.x; i < D_; i += 256) orow[i] = xr[i] * inv * w[i];
}

__global__ void rope_kernel(float* __restrict__ x, const float* __restrict__ cosT,
                            const float* __restrict__ sinT, int nheads, int total) {
    int idx = blockIdx.x * blockDim.x + threadIdx.x;
    if (idx >= total) return;
    int p = idx & 63;
    int s = (idx / (64 * nheads)) % S_;
    float c = cosT[s * 64 + p];
    float sn = sinT[s * 64 + p];
    float x1 = x[2 * idx], x2 = x[2 * idx + 1];
    x[2 * idx]     = x1 * c - x2 * sn;
    x[2 * idx + 1] = x1 * sn + x2 * c;
}

// ---------------- generic tiled SGEMM: C = op(alpha * A @ B^T [+ Res]) ----------------
// A: (M,K) rows optionally gathered via idxA; B: (N,K) row-major (weights, NT gemm)
// Res row via idxRes; C row via idxC; rowScale indexed by compact row m.
__global__ void gemm_nt(const float* __restrict__ A, const float* __restrict__ Bw,
                        float* __restrict__ C, int M, int N, int K,
                        const int* __restrict__ idxA,
                        const float* __restrict__ Res, const int* __restrict__ idxRes,
                        const int* __restrict__ idxC, const float* __restrict__ rowScale,
                        float alpha, int accumulate, const int* __restrict__ Mptr) {
    if (Mptr) M = *Mptr;
    int bm = blockIdx.y * 64;
    int bn = blockIdx.x * 64;
    if (bm >= M) return;
    __shared__ float As[16][64];
    __shared__ float Bs[16][64];
    int tid = threadIdx.x;
    int tx = tid & 15, ty = tid >> 4;
    float acc[4][4];
#pragma unroll
    for (int i = 0; i < 4; i++)
#pragma unroll
        for (int j = 0; j < 4; j++) acc[i][j] = 0.f;

    for (int k0 = 0; k0 < K; k0 += 16) {
#pragma unroll
        for (int l = 0; l < 4; l++) {
            int ii = l * 256 + tid;
            int m = ii >> 4, kk = ii & 15;
            int row = bm + m;
            float a = 0.f;
            if (row < M) {
                int ar = idxA ? idxA[row] : row;
                a = A[(size_t)ar * K + k0 + kk];
            }
            As[kk][m] = a;
            float bv = 0.f;
            if (bn + m < N) bv = Bw[(size_t)(bn + m) * K + k0 + kk];
            Bs[kk][m] = bv;
        }
        __syncthreads();
#pragma unroll
        for (int kk = 0; kk < 16; kk++) {
            float4 av = *reinterpret_cast<const float4*>(&As[kk][ty * 4]);
            float4 bv = *reinterpret_cast<const float4*>(&Bs[kk][tx * 4]);
            float a0 = av.x, a1 = av.y, a2 = av.z, a3 = av.w;
            float b0 = bv.x, b1 = bv.y, b2 = bv.z, b3 = bv.w;
            acc[0][0] += a0*b0; acc[0][1] += a0*b1; acc[0][2] += a0*b2; acc[0][3] += a0*b3;
            acc[1][0] += a1*b0; acc[1][1] += a1*b1; acc[1][2] += a1*b2; acc[1][3] += a1*b3;
            acc[2][0] += a2*b0; acc[2][1] += a2*b1; acc[2][2] += a2*b2; acc[2][3] += a2*b3;
            acc[3][0] += a3*b0; acc[3][1] += a3*b1; acc[3][2] += a3*b2; acc[3][3] += a3*b3;
        }
        __syncthreads();
    }
#pragma unroll
    for (int i = 0; i < 4; i++) {
        int row = bm + ty * 4 + i;
        if (row >= M) continue;
        int rr = idxRes ? idxRes[row] : row;
        int cr = idxC ? idxC[row] : row;
        float sc = rowScale ? rowScale[row] : 1.f;
#pragma unroll
        for (int j = 0; j < 4; j++) {
            int col = bn + tx * 4 + j;
            if (col >= N) continue;
            float val = alpha * acc[i][j];
            if (Res) val += Res[(size_t)rr * N + col];
            val *= sc;
            if (accumulate) C[(size_t)cr * N + col] += val;
            else            C[(size_t)cr * N + col] = val;
        }
    }
}

// ---------------- flash attention, fp32, 64-query tiles ----------------
// smem floats: Qt[128*65] + KV[128*65] + Sc[64*65] + mrow[64] + lrow[64] = 20928
#define ATTN_SMEM (20928 * 4)
__global__ void attn_kernel(const float* __restrict__ q, const float* __restrict__ k,
                            const float* __restrict__ v, const float* __restrict__ mask,
                            float* __restrict__ o) {
    extern __shared__ float sm[];
    float* Qt   = sm;             // K-transposed layout [d][r], pad 65
    float* KV   = sm + 8320;      // K transposed, then V row-major
    float* Sc   = sm + 16640;     // [64][65]
    float* mrow = sm + 20800;
    float* lrow = sm + 20864;

    int qt = blockIdx.x, h = blockIdx.y, b = blockIdx.z;
    int hkv = h >> 1;
    int tid = threadIdx.x;
    int q0 = qt * 64;

    for (int i = tid; i < 64 * 128; i += 256) {
        int r = i >> 7, d = i & 127;
        Qt[d * 65 + r] = q[(((size_t)b * S_ + q0 + r) * H_ + h) * HD_ + d];
    }
    if (tid < 64) { mrow[tid] = -3e38f; lrow[tid] = 0.f; }
    float acc[32];
#pragma unroll
    for (int i = 0; i < 32; i++) acc[i] = 0.f;
    int tx = tid & 15, ty = tid >> 4;
    int rg = tid >> 2, cg = tid & 3;
    __syncthreads();

    const float sca = 0.08838834764831845f;  // 1/sqrt(128)
    for (int kt = 0; kt < S_; kt += 64) {
        // load K tile transposed
        for (int i = tid; i < 64 * 128; i += 256) {
            int r = i >> 7, d = i & 127;
            KV[d * 65 + r] = k[(((size_t)b * S_ + kt + r) * HKV_ + hkv) * HD_ + d];
        }
        __syncthreads();
        // scores 64x64, 4x4 per thread
        float sc[4][4];
#pragma unroll
        for (int i = 0; i < 4; i++)
#pragma unroll
            for (int j = 0; j < 4; j++) sc[i][j] = 0.f;
        for (int d = 0; d < 128; d++) {
            float a0 = Qt[d * 65 + ty * 4 + 0];
            float a1 = Qt[d * 65 + ty * 4 + 1];
            float a2 = Qt[d * 65 + ty * 4 + 2];
            float a3 = Qt[d * 65 + ty * 4 + 3];
            float b0 = KV[d * 65 + tx * 4 + 0];
            float b1 = KV[d * 65 + tx * 4 + 1];
            float b2 = KV[d * 65 + tx * 4 + 2];
            float b3 = KV[d * 65 + tx * 4 + 3];
            sc[0][0] += a0*b0; sc[0][1] += a0*b1; sc[0][2] += a0*b2; sc[0][3] += a0*b3;
            sc[1][0] += a1*b0; sc[1][1] += a1*b1; sc[1][2] += a1*b2; sc[1][3] += a1*b3;
            sc[2][0] += a2*b0; sc[2][1] += a2*b1; sc[2][2] += a2*b2; sc[2][3] += a2*b3;
            sc[3][0] += a3*b0; sc[3][1] += a3*b1; sc[3][2] += a3*b2; sc[3][3] += a3*b3;
        }
#pragma unroll
        for (int i = 0; i < 4; i++)
#pragma unroll
            for (int j = 0; j < 4; j++) {
                int rr = ty * 4 + i, cc = tx * 4 + j;
                Sc[rr * 65 + cc] = sc[i][j] * sca + mask[(q0 + rr) * S_ + kt + cc];
            }
        __syncthreads();
        // load V row-major (overwrites K tile)
        for (int i = tid; i < 64 * 128; i += 256) {
            int r = i >> 7, d = i & 127;
            KV[r * 128 + d] = v[(((size_t)b * S_ + kt + r) * HKV_ + hkv) * HD_ + d];
        }
        // streaming softmax: 4 lanes per row
        float tm = -3e38f;
#pragma unroll
        for (int ii = 0; ii < 16; ii++) tm = fmaxf(tm, Sc[rg * 65 + cg + 4 * ii]);
        tm = fmaxf(tm, __shfl_xor_sync(0xffffffffu, tm, 1));
        tm = fmaxf(tm, __shfl_xor_sync(0xffffffffu, tm, 2));
        float mprev = mrow[rg];
        float mnew = fmaxf(mprev, tm);
        float fac = expf(mprev - mnew);
        float ls = 0.f;
#pragma unroll
        for (int ii = 0; ii < 16; ii++) {
            float p = expf(Sc[rg * 65 + cg + 4 * ii] - mnew);
            Sc[rg * 65 + cg + 4 * ii] = p;
            ls += p;
        }
        ls += __shfl_xor_sync(0xffffffffu, ls, 1);
        ls += __shfl_xor_sync(0xffffffffu, ls, 2);
        if (cg == 0) { mrow[rg] = mnew; lrow[rg] = lrow[rg] * fac + ls; }
#pragma unroll
        for (int ii = 0; ii < 32; ii++) acc[ii] *= fac;
        __syncthreads();
        // PV
        for (int j = 0; j < 64; j++) {
            float p = Sc[rg * 65 + j];
#pragma unroll
            for (int ii = 0; ii < 32; ii++) acc[ii] += p * KV[j * 128 + cg + 4 * ii];
        }
        __syncthreads();
    }
    float invl = 1.f / lrow[rg];
#pragma unroll
    for (int ii = 0; ii < 32; ii++)
        o[(((size_t)b * S_ + q0 + rg) * H_ + h) * HD_ + cg + 4 * ii] = acc[ii] * invl;
}

// ---------------- router ----------------
__global__ void router_logits_kernel(const float* __restrict__ sn, const float* __restrict__ gw,
                                     float* __restrict__ logits) {
    int t = blockIdx.x;
    float part[E_];
#pragma unroll
    for (int e = 0; e < E_; e++) part[e] = 0.f;
    const float* x = sn + (size_t)t * D_;
    for (int kk = threadIdx.x; kk < D_; kk += 256) {
        float xv = x[kk];
#pragma unroll
        for (int e = 0; e < E_; e++) part[e] += xv * gw[(size_t)e * D_ + kk];
    }
    __shared__ float red[256];
    for (int e = 0; e < E_; e++) {
        red[threadIdx.x] = part[e]; __syncthreads();
        for (int s = 128; s > 0; s >>= 1) {
            if (threadIdx.x < s) red[threadIdx.x] += red[threadIdx.x + s];
            __syncthreads();
        }
        if (threadIdx.x == 0) logits[(size_t)t * E_ + e] = red[0];
        __syncthreads();
    }
}

// softmax over sequence axis (axis=1): stats per (b, e)
__global__ void col_softmax_stats(const float* __restrict__ logits, float* __restrict__ zmax,
                                  float* __restrict__ zsum) {
    int be = blockIdx.x;       // b*E_ + e
    int b = be / E_, e = be % E_;
    __shared__ float red[256];
    float mx = -3e38f;
    for (int s = threadIdx.x; s < S_; s += 256)
        mx = fmaxf(mx, logits[((size_t)b * S_ + s) * E_ + e]);
    red[threadIdx.x] = mx; __syncthreads();
    for (int s = 128; s > 0; s >>= 1) {
        if (threadIdx.x < s) red[threadIdx.x] = fmaxf(red[threadIdx.x], red[threadIdx.x + s]);
        __syncthreads();
    }
    mx = red[0]; __syncthreads();
    float sum = 0.f;
    for (int s = threadIdx.x; s < S_; s += 256)
        sum += expf(logits[((size_t)b * S_ + s) * E_ + e] - mx);
    red[threadIdx.x] = sum; __syncthreads();
    for (int s = 128; s > 0; s >>= 1) {
        if (threadIdx.x < s) red[threadIdx.x] += red[threadIdx.x + s];
        __syncthreads();
    }
    if (threadIdx.x == 0) { zmax[be] = mx; zsum[be] = red[0]; }
}

__global__ void top2_kernel(const float* __restrict__ logits, const float* __restrict__ zmax,
                            const float* __restrict__ zsum, int* __restrict__ cnt,
                            int* __restrict__ tok, float* __restrict__ tw) {
    int t = blockIdx.x * blockDim.x + threadIdx.x;
    if (t >= T_) return;
    int b = t / S_;
    float rw[E_];
#pragma unroll
    for (int e = 0; e < E_; e++)
        rw[e] = expf(logits[(size_t)t * E_ + e] - zmax[b * E_ + e]) / zsum[b * E_ + e];
    int e0 = 0; float v0 = rw[0];
#pragma unroll
    for (int e = 1; e < E_; e++) if (rw[e] > v0) { v0 = rw[e]; e0 = e; }
    int e1 = -1; float v1 = -3e38f;
#pragma unroll
    for (int e = 0; e < E_; e++) if (e != e0 && rw[e] > v1) { v1 = rw[e]; e1 = e; }
    float inv = 1.f / (v0 + v1);
    int p0 = atomicAdd(&cnt[e0], 1);
    tok[e0 * T_ + p0] = t; tw[e0 * T_ + p0] = v0 * inv;
    int p1 = atomicAdd(&cnt[e1], 1);
    tok[e1 * T_ + p1] = t; tw[e1 * T_ + p1] = v1 * inv;
}

__global__ void silu_mul_kernel(float* __restrict__ h1, const float* __restrict__ h3,
                                const int* __restrict__ cnt) {
    int M = *cnt;
    size_t idx = (size_t)blockIdx.x * blockDim.x + threadIdx.x;
    if (idx >= (size_t)M * F_) return;
    float x = h1[idx];
    float s = x / (1.f + expf(-x));
    h1[idx] = s * h3[idx];
}

// ---------------- host launch ----------------
extern "C" void kernel_launch(void* const* d_in, const int* in_sizes, int n_in,
                              void* d_out, int out_size) {
    const float* data   = (const float*)d_in[0];
    const float* mask   = (const float*)d_in[1];
    const float* ropec  = (const float*)d_in[2];
    const float* ropes  = (const float*)d_in[3];
    const float* anw    = (const float*)d_in[4];
    const float* fnw    = (const float*)d_in[5];
    const float* wq     = (const float*)d_in[6];
    const float* wk     = (const float*)d_in[7];
    const float* wv     = (const float*)d_in[8];
    const float* wo     = (const float*)d_in[9];
    const float* gate_w = (const float*)d_in[10];
    const float* w1     = (const float*)d_in[11];
    const float* w2     = (const float*)d_in[12];
    const float* w3     = (const float*)d_in[13];
    const float* w1_a   = (const float*)d_in[14];
    const float* w1_b   = (const float*)d_in[15];
    const float* w3_a   = (const float*)d_in[16];
    const float* w3_b   = (const float*)d_in[17];
    const float* w2_a   = (const float*)d_in[18];
    const float* w2_b   = (const float*)d_in[19];
    float* out = (float*)d_out;

    float *xn, *qb, *kb, *vb, *attn, *sn, *c1, *c3, *h1, *h3, *u1, *u3, *u2;
    float *logits, *zmax, *zsum, *tw;
    int *cnt, *tok;
    cudaGetSymbolAddress((void**)&xn, g_xn);
    cudaGetSymbolAddress((void**)&qb, g_q);
    cudaGetSymbolAddress((void**)&kb, g_k);
    cudaGetSymbolAddress((void**)&vb, g_v);
    cudaGetSymbolAddress((void**)&attn, g_attn);
    cudaGetSymbolAddress((void**)&sn, g_sn);
    cudaGetSymbolAddress((void**)&c1, g_c1);
    cudaGetSymbolAddress((void**)&c3, g_c3);
    cudaGetSymbolAddress((void**)&h1, g_h1);
    cudaGetSymbolAddress((void**)&h3, g_h3);
    cudaGetSymbolAddress((void**)&u1, g_u1);
    cudaGetSymbolAddress((void**)&u3, g_u3);
    cudaGetSymbolAddress((void**)&u2, g_u2);
    cudaGetSymbolAddress((void**)&logits, g_logits);
    cudaGetSymbolAddress((void**)&zmax, g_zmax);
    cudaGetSymbolAddress((void**)&zsum, g_zsum);
    cudaGetSymbolAddress((void**)&cnt, g_cnt);
    cudaGetSymbolAddress((void**)&tok, g_tok);
    cudaGetSymbolAddress((void**)&tw, g_tw);

    reset_kernel<<<1, 32>>>(cnt);
    rmsnorm_kernel<<<T_, 256>>>(data, anw, xn);

    // QKV projections
    gemm_nt<<<dim3(D_/64, T_/64), 256>>>(xn, wq, qb, T_, D_, D_,
        nullptr, nullptr, nullptr, nullptr, nullptr, 1.f, 0, nullptr);
    gemm_nt<<<dim3((HKV_*HD_)/64, T_/64), 256>>>(xn, wk, kb, T_, HKV_*HD_, D_,
        nullptr, nullptr, nullptr, nullptr, nullptr, 1.f, 0, nullptr);
    gemm_nt<<<dim3((HKV_*HD_)/64, T_/64), 256>>>(xn, wv, vb, T_, HKV_*HD_, D_,
        nullptr, nullptr, nullptr, nullptr, nullptr, 1.f, 0, nullptr);

    rope_kernel<<<(T_*H_*64 + 255)/256, 256>>>(qb, ropec, ropes, H_, T_*H_*64);
    rope_kernel<<<(T_*HKV_*64 + 255)/256, 256>>>(kb, ropec, ropes, HKV_, T_*HKV_*64);

    cudaFuncSetAttribute(attn_kernel, cudaFuncAttributeMaxDynamicSharedMemorySize, ATTN_SMEM);
    attn_kernel<<<dim3(S_/64, H_, B_), 256, ATTN_SMEM>>>(qb, kb, vb, mask, attn);

    // out = data + attn @ wo^T
    gemm_nt<<<dim3(D_/64, T_/64), 256>>>(attn, wo, out, T_, D_, D_,
        nullptr, data, nullptr, nullptr, nullptr, 1.f, 0, nullptr);

    rmsnorm_kernel<<<T_, 256>>>(out, fnw, sn);

    router_logits_kernel<<<T_, 256>>>(sn, gate_w, logits);
    col_softmax_stats<<<B_*E_, 256>>>(logits, zmax, zsum);
    top2_kernel<<<T_/256, 256>>>(logits, zmax, zsum, cnt, tok, tw);

    // dense c1/c3
    gemm_nt<<<dim3(F_/64, T_/64), 256>>>(sn, w1, c1, T_, F_, D_,
        nullptr, nullptr, nullptr, nullptr, nullptr, 1.f, 0, nullptr);
    gemm_nt<<<dim3(F_/64, T_/64), 256>>>(sn, w3, c3, T_, F_, D_,
        nullptr, nullptr, nullptr, nullptr, nullptr, 1.f, 0, nullptr);

    for (int e = 0; e < E_; e++) {
        const int* idx = tok + e * T_;
        const float* twp = tw + e * T_;
        const int* mp = cnt + e;
        // u1 = sn[idx] @ w1_a[e]^T
        gemm_nt<<<dim3(1, T_/64), 256>>>(sn, w1_a + (size_t)e*R_*D_, u1, T_, R_, D_,
            idx, nullptr, nullptr, nullptr, nullptr, 1.f, 0, mp);
        // h1 = c1[idx] + SCALE * u1 @ w1_b[e]^T
        gemm_nt<<<dim3(F_/64, T_/64), 256>>>(u1, w1_b + (size_t)e*F_*R_, h1, T_, F_, R_,
            nullptr, c1, idx, nullptr, nullptr, SCALE_, 0, mp);
        gemm_nt<<<dim3(1, T_/64), 256>>>(sn, w3_a + (size_t)e*R_*D_, u3, T_, R_, D_,
            idx, nullptr, nullptr, nullptr, nullptr, 1.f, 0, mp);
        gemm_nt<<<dim3(F_/64, T_/64), 256>>>(u3, w3_b + (size_t)e*F_*R_, h3, T_, F_, R_,
            nullptr, c3, idx, nullptr, nullptr, SCALE_, 0, mp);
        // sr = silu(h1) * h3  (in place into h1)
        silu_mul_kernel<<<(T_*F_ + 255)/256, 256>>>(h1, h3, mp);
        // u2 = sr @ w2_a[e]^T
        gemm_nt<<<dim3(1, T_/64), 256>>>(h1, w2_a + (size_t)e*R_*F_, u2, T_, R_, F_,
            nullptr, nullptr, nullptr, nullptr, nullptr, 1.f, 0, mp);
        // out[idx] += tw * (sr @ w2^T)
        gemm_nt<<<dim3(D_/64, T_/64), 256>>>(h1, w2, out, T_, D_, F_,
            nullptr, nullptr, nullptr, idx, twp, 1.f, 1, mp);
        // out[idx] += tw * SCALE * (u2 @ w2_b[e]^T)
        gemm_nt<<<dim3(D_/64, T_/64), 256>>>(u2, w2_b + (size_t)e*D_*R_, out, T_, D_, R_,
            nullptr, nullptr, nullptr, idx, twp, SCALE_, 1, mp);
    }
}

// round 2
// speedup vs baseline: 3.2358x; 3.2358x over previous
#include <cuda_runtime.h>
#include <math.h>

#define B_ 2
#define S_ 1024
#define D_ 2048
#define H_ 16
#define HKV_ 8
#define HD_ 128
#define F_ 5632
#define E_ 8
#define R_ 16
#define T_ (B_*S_)
#define EPS_ 1e-5f
#define SCALE_ 2.0f

// ---------------- device scratch (static, allocation-free) ----------------
__device__ float g_xn[T_*D_];
__device__ float g_q[T_*D_];
__device__ float g_k[T_*HKV_*HD_];
__device__ float g_v[T_*HKV_*HD_];
__device__ float g_attn[T_*D_];
__device__ float g_sn[T_*D_];
__device__ float g_c1[T_*F_];
__device__ float g_c3[T_*F_];
__device__ float g_h1[2*T_*F_];     // compact rows (sum cnt = 2T), reused as sr
__device__ float g_h3[2*T_*F_];
__device__ float g_expout[2*T_*D_];
__device__ float g_u1[2*T_*R_];
__device__ float g_u3[2*T_*R_];
__device__ float g_u2[2*T_*R_];
__device__ float g_logits[T_*E_];
__device__ float g_zmax[B_*E_];
__device__ float g_zsum[B_*E_];
__device__ int   g_cnt[E_];
__device__ int   g_off[E_];
__device__ int   g_tok[E_*T_];
__device__ int   g_sel[2*T_];
__device__ int   g_pos[2*T_];
__device__ float g_wgt[2*T_];

// ---------------- small kernels ----------------
__global__ void reset_kernel(int* cnt) {
    if (threadIdx.x < E_) cnt[threadIdx.x] = 0;
}

__global__ void rmsnorm_kernel(const float* __restrict__ x, const float* __restrict__ w,
                               float* __restrict__ out) {
    int row = blockIdx.x;
    const float* xr = x + (size_t)row * D_;
    float ss = 0.f;
    for (int i = threadIdx.x; i < D_; i += 256) { float v = xr[i]; ss += v * v; }
    __shared__ float red[256];
    red[threadIdx.x] = ss; __syncthreads();
    for (int s = 128; s > 0; s >>= 1) {
        if (threadIdx.x < s) red[threadIdx.x] += red[threadIdx.x + s];
        __syncthreads();
    }
    float inv = rsqrtf(red[0] / (float)D_ + EPS_);
    float* orow = out + (size_t)row * D_;
    for (int i = threadIdx.x; i < D_; i += 256) orow[i] = xr[i] * inv * w[i];
}

__global__ void rope_kernel(float* __restrict__ x, const float* __restrict__ cosT,
                            const float* __restrict__ sinT, int nheads, int total) {
    int idx = blockIdx.x * blockDim.x + threadIdx.x;
    if (idx >= total) return;
    int p = idx & 63;
    int s = (idx / (64 * nheads)) % S_;
    float c = cosT[s * 64 + p];
    float sn = sinT[s * 64 + p];
    float x1 = x[2 * idx], x2 = x[2 * idx + 1];
    x[2 * idx]     = x1 * c - x2 * sn;
    x[2 * idx + 1] = x1 * sn + x2 * c;
}

// ---------------- big SGEMM: 128x128 tile, 8x8 microtile, double-buffered ----------------
// C[(base+row)*N + col] (=|+=) alpha * A_row @ Bz^T (+ Res[row*N+col])
// A_row: tok ? A[tok[row]] : A[base+row]; Bz = Bw + z*strideB (N,K) row-major.
// N must be a multiple of 128, K a multiple of 16.
__global__ __launch_bounds__(256, 2)
void gemm_big(const float* __restrict__ A, const float* __restrict__ Bw,
              float* __restrict__ C, int M, int N, int K,
              const int* __restrict__ tokIdx,
              const float* __restrict__ Res,
              float alpha, int accumulate,
              const int* __restrict__ Mcnt, const int* __restrict__ Moff,
              size_t strideB) {
    int z = blockIdx.z;
    if (Mcnt) M = Mcnt[z];
    int bm = blockIdx.y * 128;
    if (bm >= M) return;
    int bn = blockIdx.x * 128;
    int base = Moff ? Moff[z] : 0;
    const int* tok = tokIdx ? tokIdx + z * T_ : nullptr;
    const float* Bz = Bw + (size_t)z * strideB;

    __shared__ float As[2][16][128];
    __shared__ float Bs[2][16][128];

    int tid = threadIdx.x;
    int tx = tid & 15, ty = tid >> 4;

    // loader indices: 512 float4 chunks per 128x16 tile, 2 per thread
    int r0 = tid >> 2;            // 0..63
    int r1 = r0 + 64;             // 64..127
    int kq0 = (tid & 3) * 4;      // 0,4,8,12

    const float* aPtr0 = nullptr;
    const float* aPtr1 = nullptr;
    {
        int g0 = bm + r0, g1 = bm + r1;
        if (g0 < M) aPtr0 = A + (size_t)(tok ? tok[g0] : base + g0) * K + kq0;
        if (g1 < M) aPtr1 = A + (size_t)(tok ? tok[g1] : base + g1) * K + kq0;
    }
    const float* bPtr0 = Bz + (size_t)(bn + r0) * K + kq0;
    const float* bPtr1 = Bz + (size_t)(bn + r1) * K + kq0;

    float acc[8][8];
#pragma unroll
    for (int i = 0; i < 8; i++)
#pragma unroll
        for (int j = 0; j < 8; j++) acc[i][j] = 0.f;

#define LOAD_TILE(buf, k0) do {                                               \
        float4 va0 = make_float4(0.f,0.f,0.f,0.f);                            \
        float4 va1 = make_float4(0.f,0.f,0.f,0.f);                            \
        if (aPtr0) va0 = *reinterpret_cast<const float4*>(aPtr0 + (k0));      \
        if (aPtr1) va1 = *reinterpret_cast<const float4*>(aPtr1 + (k0));      \
        float4 vb0 = *reinterpret_cast<const float4*>(bPtr0 + (k0));          \
        float4 vb1 = *reinterpret_cast<const float4*>(bPtr1 + (k0));          \
        As[buf][kq0+0][r0] = va0.x; As[buf][kq0+1][r0] = va0.y;               \
        As[buf][kq0+2][r0] = va0.z; As[buf][kq0+3][r0] = va0.w;               \
        As[buf][kq0+0][r1] = va1.x; As[buf][kq0+1][r1] = va1.y;               \
        As[buf][kq0+2][r1] = va1.z; As[buf][kq0+3][r1] = va1.w;               \
        Bs[buf][kq0+0][r0] = vb0.x; Bs[buf][kq0+1][r0] = vb0.y;               \
        Bs[buf][kq0+2][r0] = vb0.z; Bs[buf][kq0+3][r0] = vb0.w;               \
        Bs[buf][kq0+0][r1] = vb1.x; Bs[buf][kq0+1][r1] = vb1.y;               \
        Bs[buf][kq0+2][r1] = vb1.z; Bs[buf][kq0+3][r1] = vb1.w;               \
    } while (0)

    LOAD_TILE(0, 0);
    __syncthreads();

    int nk = K / 16;
    for (int t = 0; t < nk; t++) {
        int cur = t & 1;
        if (t + 1 < nk) LOAD_TILE(cur ^ 1, (t + 1) * 16);
#pragma unroll
        for (int kk = 0; kk < 16; kk++) {
            float4 a0 = *reinterpret_cast<const float4*>(&As[cur][kk][ty * 4]);
            float4 a1 = *reinterpret_cast<const float4*>(&As[cur][kk][64 + ty * 4]);
            float4 b0 = *reinterpret_cast<const float4*>(&Bs[cur][kk][tx * 4]);
            float4 b1 = *reinterpret_cast<const float4*>(&Bs[cur][kk][64 + tx * 4]);
            float a[8] = {a0.x,a0.y,a0.z,a0.w,a1.x,a1.y,a1.z,a1.w};
            float b[8] = {b0.x,b0.y,b0.z,b0.w,b1.x,b1.y,b1.z,b1.w};
#pragma unroll
            for (int i = 0; i < 8; i++)
#pragma unroll
                for (int j = 0; j < 8; j++) acc[i][j] += a[i] * b[j];
        }
        __syncthreads();
    }
#undef LOAD_TILE

#pragma unroll
    for (int i = 0; i < 8; i++) {
        int r = bm + ty * 4 + (i & 3) + (i >> 2) * 64;
        if (r >= M) continue;
        size_t crow = (size_t)(base + r) * N;
        size_t rrow = (size_t)r * N;
#pragma unroll
        for (int h = 0; h < 2; h++) {
            int col = bn + h * 64 + tx * 4;
            float4 v;
            v.x = alpha * acc[i][h*4+0];
            v.y = alpha * acc[i][h*4+1];
            v.z = alpha * acc[i][h*4+2];
            v.w = alpha * acc[i][h*4+3];
            if (Res) {
                float4 rv = *reinterpret_cast<const float4*>(Res + rrow + col);
                v.x += rv.x; v.y += rv.y; v.z += rv.z; v.w += rv.w;
            }
            if (accumulate) {
                float4 cv = *reinterpret_cast<const float4*>(C + crow + col);
                v.x += cv.x; v.y += cv.y; v.z += cv.z; v.w += cv.w;
            }
            *reinterpret_cast<float4*>(C + crow + col) = v;
        }
    }
}

// ---------------- small SGEMM: 64x64 tile, expert-batched ----------------
__global__ void gemm_small(const float* __restrict__ A, const float* __restrict__ Bw,
                           float* __restrict__ C, int N, int K,
                           const int* __restrict__ tokIdx, int gatherA,
                           const float* __restrict__ Res,
                           float alpha, int accumulate,
                           const int* __restrict__ Mcnt, const int* __restrict__ Moff,
                           size_t strideB) {
    int z = blockIdx.z;
    int M = Mcnt[z];
    int bm = blockIdx.y * 64;
    if (bm >= M) return;
    int bn = blockIdx.x * 64;
    int base = Moff[z];
    const int* tok = tokIdx + z * T_;
    const float* Bz = Bw + (size_t)z * strideB;

    __shared__ float As[16][64];
    __shared__ float Bs[16][64];
    int tid = threadIdx.x;
    int tx = tid & 15, ty = tid >> 4;
    float acc[4][4];
#pragma unroll
    for (int i = 0; i < 4; i++)
#pragma unroll
        for (int j = 0; j < 4; j++) acc[i][j] = 0.f;

    for (int k0 = 0; k0 < K; k0 += 16) {
#pragma unroll
        for (int l = 0; l < 4; l++) {
            int ii = l * 256 + tid;
            int m = ii >> 4, kk = ii & 15;
            int row = bm + m;
            float a = 0.f;
            if (row < M) {
                int ar = gatherA ? tok[row] : base + row;
                a = A[(size_t)ar * K + k0 + kk];
            }
            As[kk][m] = a;
            float bv = 0.f;
            if (bn + m < N) bv = Bz[(size_t)(bn + m) * K + k0 + kk];
            Bs[kk][m] = bv;
        }
        __syncthreads();
#pragma unroll
        for (int kk = 0; kk < 16; kk++) {
            float4 av = *reinterpret_cast<const float4*>(&As[kk][ty * 4]);
            float4 bv = *reinterpret_cast<const float4*>(&Bs[kk][tx * 4]);
            float a0 = av.x, a1 = av.y, a2 = av.z, a3 = av.w;
            float b0 = bv.x, b1 = bv.y, b2 = bv.z, b3 = bv.w;
            acc[0][0] += a0*b0; acc[0][1] += a0*b1; acc[0][2] += a0*b2; acc[0][3] += a0*b3;
            acc[1][0] += a1*b0; acc[1][1] += a1*b1; acc[1][2] += a1*b2; acc[1][3] += a1*b3;
            acc[2][0] += a2*b0; acc[2][1] += a2*b1; acc[2][2] += a2*b2; acc[2][3] += a2*b3;
            acc[3][0] += a3*b0; acc[3][1] += a3*b1; acc[3][2] += a3*b2; acc[3][3] += a3*b3;
        }
        __syncthreads();
    }
#pragma unroll
    for (int i = 0; i < 4; i++) {
        int row = bm + ty * 4 + i;
        if (row >= M) continue;
        size_t crow = (size_t)(base + row) * N;
#pragma unroll
        for (int j = 0; j < 4; j++) {
            int col = bn + tx * 4 + j;
            if (col >= N) continue;
            float val = alpha * acc[i][j];
            if (Res) val += Res[(size_t)tok[row] * N + col];
            if (accumulate) C[crow + col] += val;
            else            C[crow + col] = val;
        }
    }
}

// ---------------- flash attention, fp32, 64-query tiles ----------------
#define ATTN_SMEM (20928 * 4)
__global__ void attn_kernel(const float* __restrict__ q, const float* __restrict__ k,
                            const float* __restrict__ v, const float* __restrict__ mask,
                            float* __restrict__ o) {
    extern __shared__ float sm[];
    float* Qt   = sm;
    float* KV   = sm + 8320;
    float* Sc   = sm + 16640;
    float* mrow = sm + 20800;
    float* lrow = sm + 20864;

    int qt = blockIdx.x, h = blockIdx.y, b = blockIdx.z;
    int hkv = h >> 1;
    int tid = threadIdx.x;
    int q0 = qt * 64;

    for (int i = tid; i < 64 * 128; i += 256) {
        int r = i >> 7, d = i & 127;
        Qt[d * 65 + r] = q[(((size_t)b * S_ + q0 + r) * H_ + h) * HD_ + d];
    }
    if (tid < 64) { mrow[tid] = -3e38f; lrow[tid] = 0.f; }
    float acc[32];
#pragma unroll
    for (int i = 0; i < 32; i++) acc[i] = 0.f;
    int tx = tid & 15, ty = tid >> 4;
    int rg = tid >> 2, cg = tid & 3;
    __syncthreads();

    const float sca = 0.08838834764831845f;
    for (int kt = 0; kt < S_; kt += 64) {
        for (int i = tid; i < 64 * 128; i += 256) {
            int r = i >> 7, d = i & 127;
            KV[d * 65 + r] = k[(((size_t)b * S_ + kt + r) * HKV_ + hkv) * HD_ + d];
        }
        __syncthreads();
        float sc[4][4];
#pragma unroll
        for (int i = 0; i < 4; i++)
#pragma unroll
            for (int j = 0; j < 4; j++) sc[i][j] = 0.f;
        for (int d = 0; d < 128; d++) {
            float a0 = Qt[d * 65 + ty * 4 + 0];
            float a1 = Qt[d * 65 + ty * 4 + 1];
            float a2 = Qt[d * 65 + ty * 4 + 2];
            float a3 = Qt[d * 65 + ty * 4 + 3];
            float b0 = KV[d * 65 + tx * 4 + 0];
            float b1 = KV[d * 65 + tx * 4 + 1];
            float b2 = KV[d * 65 + tx * 4 + 2];
            float b3 = KV[d * 65 + tx * 4 + 3];
            sc[0][0] += a0*b0; sc[0][1] += a0*b1; sc[0][2] += a0*b2; sc[0][3] += a0*b3;
            sc[1][0] += a1*b0; sc[1][1] += a1*b1; sc[1][2] += a1*b2; sc[1][3] += a1*b3;
            sc[2][0] += a2*b0; sc[2][1] += a2*b1; sc[2][2] += a2*b2; sc[2][3] += a2*b3;
            sc[3][0] += a3*b0; sc[3][1] += a3*b1; sc[3][2] += a3*b2; sc[3][3] += a3*b3;
        }
#pragma unroll
        for (int i = 0; i < 4; i++)
#pragma unroll
            for (int j = 0; j < 4; j++) {
                int rr = ty * 4 + i, cc = tx * 4 + j;
                Sc[rr * 65 + cc] = sc[i][j] * sca + mask[(q0 + rr) * S_ + kt + cc];
            }
        __syncthreads();
        for (int i = tid; i < 64 * 128; i += 256) {
            int r = i >> 7, d = i & 127;
            KV[r * 128 + d] = v[(((size_t)b * S_ + kt + r) * HKV_ + hkv) * HD_ + d];
        }
        float tm = -3e38f;
#pragma unroll
        for (int ii = 0; ii < 16; ii++) tm = fmaxf(tm, Sc[rg * 65 + cg + 4 * ii]);
        tm = fmaxf(tm, __shfl_xor_sync(0xffffffffu, tm, 1));
        tm = fmaxf(tm, __shfl_xor_sync(0xffffffffu, tm, 2));
        float mprev = mrow[rg];
        float mnew = fmaxf(mprev, tm);
        float fac = expf(mprev - mnew);
        float ls = 0.f;
#pragma unroll
        for (int ii = 0; ii < 16; ii++) {
            float p = expf(Sc[rg * 65 + cg + 4 * ii] - mnew);
            Sc[rg * 65 + cg + 4 * ii] = p;
            ls += p;
        }
        ls += __shfl_xor_sync(0xffffffffu, ls, 1);
        ls += __shfl_xor_sync(0xffffffffu, ls, 2);
        if (cg == 0) { mrow[rg] = mnew; lrow[rg] = lrow[rg] * fac + ls; }
#pragma unroll
        for (int ii = 0; ii < 32; ii++) acc[ii] *= fac;
        __syncthreads();
        for (int j = 0; j < 64; j++) {
            float p = Sc[rg * 65 + j];
#pragma unroll
            for (int ii = 0; ii < 32; ii++) acc[ii] += p * KV[j * 128 + cg + 4 * ii];
        }
        __syncthreads();
    }
    float invl = 1.f / lrow[rg];
#pragma unroll
    for (int ii = 0; ii < 32; ii++)
        o[(((size_t)b * S_ + q0 + rg) * H_ + h) * HD_ + cg + 4 * ii] = acc[ii] * invl;
}

// ---------------- router ----------------
__global__ void router_logits_kernel(const float* __restrict__ sn, const float* __restrict__ gw,
                                     float* __restrict__ logits) {
    int t = blockIdx.x;
    float part[E_];
#pragma unroll
    for (int e = 0; e < E_; e++) part[e] = 0.f;
    const float* x = sn + (size_t)t * D_;
    for (int kk = threadIdx.x; kk < D_; kk += 256) {
        float xv = x[kk];
#pragma unroll
        for (int e = 0; e < E_; e++) part[e] += xv * gw[(size_t)e * D_ + kk];
    }
    __shared__ float red[256];
    for (int e = 0; e < E_; e++) {
        red[threadIdx.x] = part[e]; __syncthreads();
        for (int s = 128; s > 0; s >>= 1) {
            if (threadIdx.x < s) red[threadIdx.x] += red[threadIdx.x + s];
            __syncthreads();
        }
        if (threadIdx.x == 0) logits[(size_t)t * E_ + e] = red[0];
        __syncthreads();
    }
}

__global__ void col_softmax_stats(const float* __restrict__ logits, float* __restrict__ zmax,
                                  float* __restrict__ zsum) {
    int be = blockIdx.x;
    int b = be / E_, e = be % E_;
    __shared__ float red[256];
    float mx = -3e38f;
    for (int s = threadIdx.x; s < S_; s += 256)
        mx = fmaxf(mx, logits[((size_t)b * S_ + s) * E_ + e]);
    red[threadIdx.x] = mx; __syncthreads();
    for (int s = 128; s > 0; s >>= 1) {
        if (threadIdx.x < s) red[threadIdx.x] = fmaxf(red[threadIdx.x], red[threadIdx.x + s]);
        __syncthreads();
    }
    mx = red[0]; __syncthreads();
    float sum = 0.f;
    for (int s = threadIdx.x; s < S_; s += 256)
        sum += expf(logits[((size_t)b * S_ + s) * E_ + e] - mx);
    red[threadIdx.x] = sum; __syncthreads();
    for (int s = 128; s > 0; s >>= 1) {
        if (threadIdx.x < s) red[threadIdx.x] += red[threadIdx.x + s];
        __syncthreads();
    }
    if (threadIdx.x == 0) { zmax[be] = mx; zsum[be] = red[0]; }
}

__global__ void top2_kernel(const float* __restrict__ logits, const float* __restrict__ zmax,
                            const float* __restrict__ zsum, int* __restrict__ cnt,
                            int* __restrict__ tok, int* __restrict__ sel,
                            int* __restrict__ pos, float* __restrict__ wgt) {
    int t = blockIdx.x * blockDim.x + threadIdx.x;
    if (t >= T_) return;
    int b = t / S_;
    float rw[E_];
#pragma unroll
    for (int e = 0; e < E_; e++)
        rw[e] = expf(logits[(size_t)t * E_ + e] - zmax[b * E_ + e]) / zsum[b * E_ + e];
    int e0 = 0; float v0 = rw[0];
#pragma unroll
    for (int e = 1; e < E_; e++) if (rw[e] > v0) { v0 = rw[e]; e0 = e; }
    int e1 = -1; float v1 = -3e38f;
#pragma unroll
    for (int e = 0; e < E_; e++) if (e != e0 && rw[e] > v1) { v1 = rw[e]; e1 = e; }
    float inv = 1.f / (v0 + v1);
    int p0 = atomicAdd(&cnt[e0], 1);
    tok[e0 * T_ + p0] = t;
    int p1 = atomicAdd(&cnt[e1], 1);
    tok[e1 * T_ + p1] = t;
    sel[2*t] = e0; pos[2*t] = p0; wgt[2*t] = v0 * inv;
    sel[2*t+1] = e1; pos[2*t+1] = p1; wgt[2*t+1] = v1 * inv;
}

__global__ void offsets_kernel(const int* __restrict__ cnt, int* __restrict__ off) {
    if (threadIdx.x == 0) {
        int s = 0;
        for (int e = 0; e < E_; e++) { off[e] = s; s += cnt[e]; }
    }
}

__global__ void silu_kernel(float* __restrict__ h1, const float* __restrict__ h3,
                            const int* __restrict__ cnt, const int* __restrict__ off) {
    int z = blockIdx.y;
    int row = blockIdx.x;
    if (row >= cnt[z]) return;
    size_t g = (size_t)(off[z] + row) * F_;
    for (int i = threadIdx.x; i < F_; i += 256) {
        float x = h1[g + i];
        h1[g + i] = (x / (1.f + expf(-x))) * h3[g + i];
    }
}

__global__ void gather_kernel(const float* __restrict__ expout, const int* __restrict__ off,
                              const int* __restrict__ sel, const int* __restrict__ pos,
                              const float* __restrict__ wgt, float* __restrict__ out) {
    int t = blockIdx.x;
    int e0 = sel[2*t], e1 = sel[2*t+1];
    size_t r0 = (size_t)(off[e0] + pos[2*t]) * D_;
    size_t r1 = (size_t)(off[e1] + pos[2*t+1]) * D_;
    float w0 = wgt[2*t], w1 = wgt[2*t+1];
    for (int i = threadIdx.x; i < D_; i += 256)
        out[(size_t)t * D_ + i] += w0 * expout[r0 + i] + w1 * expout[r1 + i];
}

// ---------------- host launch ----------------
extern "C" void kernel_launch(void* const* d_in, const int* in_sizes, int n_in,
                              void* d_out, int out_size) {
    const float* data   = (const float*)d_in[0];
    const float* mask   = (const float*)d_in[1];
    const float* ropec  = (const float*)d_in[2];
    const float* ropes  = (const float*)d_in[3];
    const float* anw    = (const float*)d_in[4];
    const float* fnw    = (const float*)d_in[5];
    const float* wq     = (const float*)d_in[6];
    const float* wk     = (const float*)d_in[7];
    const float* wv     = (const float*)d_in[8];
    const float* wo     = (const float*)d_in[9];
    const float* gate_w = (const float*)d_in[10];
    const float* w1     = (const float*)d_in[11];
    const float* w2     = (const float*)d_in[12];
    const float* w3     = (const float*)d_in[13];
    const float* w1_a   = (const float*)d_in[14];
    const float* w1_b   = (const float*)d_in[15];
    const float* w3_a   = (const float*)d_in[16];
    const float* w3_b   = (const float*)d_in[17];
    const float* w2_a   = (const float*)d_in[18];
    const float* w2_b   = (const float*)d_in[19];
    float* out = (float*)d_out;

    float *xn, *qb, *kb, *vb, *attn, *sn, *c1, *c3, *h1, *h3, *u1, *u3, *u2;
    float *logits, *zmax, *zsum, *wgt, *expout;
    int *cnt, *off, *tok, *sel, *pos;
    cudaGetSymbolAddress((void**)&xn, g_xn);
    cudaGetSymbolAddress((void**)&qb, g_q);
    cudaGetSymbolAddress((void**)&kb, g_k);
    cudaGetSymbolAddress((void**)&vb, g_v);
    cudaGetSymbolAddress((void**)&attn, g_attn);
    cudaGetSymbolAddress((void**)&sn, g_sn);
    cudaGetSymbolAddress((void**)&c1, g_c1);
    cudaGetSymbolAddress((void**)&c3, g_c3);
    cudaGetSymbolAddress((void**)&h1, g_h1);
    cudaGetSymbolAddress((void**)&h3, g_h3);
    cudaGetSymbolAddress((void**)&u1, g_u1);
    cudaGetSymbolAddress((void**)&u3, g_u3);
    cudaGetSymbolAddress((void**)&u2, g_u2);
    cudaGetSymbolAddress((void**)&expout, g_expout);
    cudaGetSymbolAddress((void**)&logits, g_logits);
    cudaGetSymbolAddress((void**)&zmax, g_zmax);
    cudaGetSymbolAddress((void**)&zsum, g_zsum);
    cudaGetSymbolAddress((void**)&cnt, g_cnt);
    cudaGetSymbolAddress((void**)&off, g_off);
    cudaGetSymbolAddress((void**)&tok, g_tok);
    cudaGetSymbolAddress((void**)&sel, g_sel);
    cudaGetSymbolAddress((void**)&pos, g_pos);
    cudaGetSymbolAddress((void**)&wgt, g_wgt);

    reset_kernel<<<1, 32>>>(cnt);
    rmsnorm_kernel<<<T_, 256>>>(data, anw, xn);

    // QKV projections
    gemm_big<<<dim3(D_/128, T_/128, 1), 256>>>(xn, wq, qb, T_, D_, D_,
        nullptr, nullptr, 1.f, 0, nullptr, nullptr, 0);
    gemm_big<<<dim3((HKV_*HD_)/128, T_/128, 1), 256>>>(xn, wk, kb, T_, HKV_*HD_, D_,
        nullptr, nullptr, 1.f, 0, nullptr, nullptr, 0);
    gemm_big<<<dim3((HKV_*HD_)/128, T_/128, 1), 256>>>(xn, wv, vb, T_, HKV_*HD_, D_,
        nullptr, nullptr, 1.f, 0, nullptr, nullptr, 0);

    rope_kernel<<<(T_*H_*64 + 255)/256, 256>>>(qb, ropec, ropes, H_, T_*H_*64);
    rope_kernel<<<(T_*HKV_*64 + 255)/256, 256>>>(kb, ropec, ropes, HKV_, T_*HKV_*64);

    cudaFuncSetAttribute(attn_kernel, cudaFuncAttributeMaxDynamicSharedMemorySize, ATTN_SMEM);
    attn_kernel<<<dim3(S_/64, H_, B_), 256, ATTN_SMEM>>>(qb, kb, vb, mask, attn);

    // out = data + attn @ wo^T
    gemm_big<<<dim3(D_/128, T_/128, 1), 256>>>(attn, wo, out, T_, D_, D_,
        nullptr, data, 1.f, 0, nullptr, nullptr, 0);

    rmsnorm_kernel<<<T_, 256>>>(out, fnw, sn);

    router_logits_kernel<<<T_, 256>>>(sn, gate_w, logits);
    col_softmax_stats<<<B_*E_, 256>>>(logits, zmax, zsum);
    top2_kernel<<<T_/256, 256>>>(logits, zmax, zsum, cnt, tok, sel, pos, wgt);
    offsets_kernel<<<1, 32>>>(cnt, off);

    // dense c1/c3
    gemm_big<<<dim3(F_/128, T_/128, 1), 256>>>(sn, w1, c1, T_, F_, D_,
        nullptr, nullptr, 1.f, 0, nullptr, nullptr, 0);
    gemm_big<<<dim3(F_/128, T_/128, 1), 256>>>(sn, w3, c3, T_, F_, D_,
        nullptr, nullptr, 1.f, 0, nullptr, nullptr, 0);

    // ---- expert-batched LoRA path (z = expert) ----
    // u1 = sn[tok] @ w1_a^T
    gemm_small<<<dim3(1, T_/64, E_), 256>>>(sn, w1_a, u1, R_, D_,
        tok, 1, nullptr, 1.f, 0, cnt, off, (size_t)R_*D_);
    // h1 = c1[tok] + SCALE * u1 @ w1_b^T
    gemm_small<<<dim3(F_/64, T_/64, E_), 256>>>(u1, w1_b, h1, F_, R_,
        tok, 0, c1, SCALE_, 0, cnt, off, (size_t)F_*R_);
    gemm_small<<<dim3(1, T_/64, E_), 256>>>(sn, w3_a, u3, R_, D_,
        tok, 1, nullptr, 1.f, 0, cnt, off, (size_t)R_*D_);
    gemm_small<<<dim3(F_/64, T_/64, E_), 256>>>(u3, w3_b, h3, F_, R_,
        tok, 0, c3, SCALE_, 0, cnt, off, (size_t)F_*R_);
    // sr = silu(h1) * h3 (in place)
    silu_kernel<<<dim3(T_, E_), 256>>>(h1, h3, cnt, off);
    // u2 = sr @ w2_a^T
    gemm_small<<<dim3(1, T_/64, E_), 256>>>(h1, w2_a, u2, R_, F_,
        tok, 0, nullptr, 1.f, 0, cnt, off, (size_t)R_*F_);
    // expout = sr @ w2^T  (big, w2 shared across experts)
    gemm_big<<<dim3(D_/128, T_/128, E_), 256>>>(h1, w2, expout, T_, D_, F_,
        nullptr, nullptr, 1.f, 0, cnt, off, 0);
    // expout += SCALE * u2 @ w2_b^T
    gemm_small<<<dim3(D_/64, T_/64, E_), 256>>>(u2, w2_b, expout, D_, R_,
        tok, 0, nullptr, SCALE_, 1, cnt, off, (size_t)D_*R_);

    // out[t] += w0*expout[slot0] + w1*expout[slot1]
    gather_kernel<<<T_, 256>>>(expout, off, sel, pos, wgt, out);
}

// round 7
// speedup vs baseline: 5.2919x; 1.6354x over previous
#include <cuda_runtime.h>
#include <math.h>
#include <stdint.h>

#define B_ 2
#define S_ 1024
#define D_ 2048
#define H_ 16
#define HKV_ 8
#define HD_ 128
#define F_ 5632
#define E_ 8
#define R_ 16
#define T_ (B_*S_)
#define EPS_ 1e-5f
#define SCALE_ 2.0f

// ---------------- device scratch (static, allocation-free) ----------------
__device__ float g_xn[T_*D_];
__device__ float g_q[T_*D_];
__device__ float g_k[T_*HKV_*HD_];
__device__ float g_v[T_*HKV_*HD_];
__device__ float g_attn[T_*D_];
__device__ float g_sn[T_*D_];
__device__ float g_c1[T_*F_];
__device__ float g_c3[T_*F_];
__device__ float g_h1[2*T_*F_];
__device__ float g_h3[2*T_*F_];
__device__ float g_expout[2*T_*D_];
__device__ float g_u1[2*T_*R_];
__device__ float g_u3[2*T_*R_];
__device__ float g_u2[2*T_*R_];
__device__ float g_logits[T_*E_];
__device__ float g_zmax[B_*E_];
__device__ float g_zsum[B_*E_];
__device__ int   g_cnt[E_];
__device__ int   g_off[E_];
__device__ int   g_tok[E_*T_];
__device__ int   g_sel[2*T_];
__device__ int   g_pos[2*T_];
__device__ float g_wgt[2*T_];

// ---------------- helpers ----------------
__device__ __forceinline__ float tf32r(float x) {
    uint32_t y;
    asm("cvt.rna.tf32.f32 %0, %1;" : "=r"(y) : "f"(x));
    return __uint_as_float(y);
}
__device__ __forceinline__ void mma_tf32(float& d0, float& d1, float& d2, float& d3,
                                         float a0, float a1, float a2, float a3,
                                         float b0, float b1) {
    asm volatile(
        "mma.sync.aligned.m16n8k8.row.col.f32.tf32.tf32.f32 "
        "{%0,%1,%2,%3}, {%4,%5,%6,%7}, {%8,%9}, {%0,%1,%2,%3};"
        : "+f"(d0), "+f"(d1), "+f"(d2), "+f"(d3)
        : "r"(__float_as_uint(a0)), "r"(__float_as_uint(a1)),
          "r"(__float_as_uint(a2)), "r"(__float_as_uint(a3)),
          "r"(__float_as_uint(b0)), "r"(__float_as_uint(b1)));
}

// ---------------- tf32 mma.sync GEMM: C[(base+m), n] (=|) A[(base+m)] @ Bw[n]^T (+Res) ----------------
// 128x128 CTA tile, 8 warps (2x4), 64x32 warp tile, K chunks of 16, double-buffered.
// N multiple of 128, K multiple of 16.
__global__ __launch_bounds__(256, 2)
void gemm_mma(const float* __restrict__ A, const float* __restrict__ Bw,
              float* __restrict__ C, int M, int N, int K,
              const float* __restrict__ Res,
              const int* __restrict__ Mcnt, const int* __restrict__ Moff) {
    __shared__ float As[2][128][20];
    __shared__ float Bs[2][128][20];

    int z = blockIdx.z;
    if (Mcnt) M = Mcnt[z];
    int bm = blockIdx.y * 128;
    if (bm >= M) return;
    int bn = blockIdx.x * 128;
    int base = Moff ? Moff[z] : 0;

    int tid = threadIdx.x, wid = tid >> 5, lid = tid & 31;
    int wm = wid >> 2, wn = wid & 3;           // 2 x 4 warp grid
    int m0 = wm * 64, n0 = wn * 32;
    int lr = lid >> 2, lc = lid & 3;

    float acc[4][4][4];
#pragma unroll
    for (int i = 0; i < 4; i++)
#pragma unroll
        for (int j = 0; j < 4; j++)
#pragma unroll
            for (int q = 0; q < 4; q++) acc[i][j][q] = 0.f;

    int grA = tid >> 2;                        // 0..63 (+64 on second it)
    int gc  = (tid & 3) * 4;

    float4 pa[2], pb[2];
    const float4 z4 = make_float4(0.f, 0.f, 0.f, 0.f);

#define PREF(k0) do {                                                           \
        _Pragma("unroll")                                                       \
        for (int it = 0; it < 2; it++) {                                        \
            int gr = it * 64 + grA;                                             \
            pa[it] = z4;                                                        \
            if (bm + gr < M)                                                    \
                pa[it] = *reinterpret_cast<const float4*>(                      \
                    A + (size_t)(base + bm + gr) * K + (k0) + gc);              \
            pb[it] = *reinterpret_cast<const float4*>(                          \
                    Bw + (size_t)(bn + gr) * K + (k0) + gc);                    \
        }                                                                       \
    } while (0)

#define STORE(buf) do {                                                         \
        _Pragma("unroll")                                                       \
        for (int it = 0; it < 2; it++) {                                        \
            int gr = it * 64 + grA;                                             \
            float4 ca = make_float4(tf32r(pa[it].x), tf32r(pa[it].y),           \
                                    tf32r(pa[it].z), tf32r(pa[it].w));          \
            float4 cb = make_float4(tf32r(pb[it].x), tf32r(pb[it].y),           \
                                    tf32r(pb[it].z), tf32r(pb[it].w));          \
            *reinterpret_cast<float4*>(&As[buf][gr][gc]) = ca;                  \
            *reinterpret_cast<float4*>(&Bs[buf][gr][gc]) = cb;                  \
        }                                                                       \
    } while (0)

#define COMPUTE(buf) do {                                                       \
        _Pragma("unroll")                                                       \
        for (int ks = 0; ks < 2; ks++) {                                        \
            int kk = ks * 8;                                                    \
            float a[4][4], b[4][2];                                             \
            _Pragma("unroll")                                                   \
            for (int mt = 0; mt < 4; mt++) {                                    \
                a[mt][0] = As[buf][m0 + mt*16 + lr][kk + lc];                   \
                a[mt][1] = As[buf][m0 + mt*16 + lr + 8][kk + lc];               \
                a[mt][2] = As[buf][m0 + mt*16 + lr][kk + lc + 4];               \
                a[mt][3] = As[buf][m0 + mt*16 + lr + 8][kk + lc + 4];           \
            }                                                                   \
            _Pragma("unroll")                                                   \
            for (int nt = 0; nt < 4; nt++) {                                    \
                b[nt][0] = Bs[buf][n0 + nt*8 + lr][kk + lc];                    \
                b[nt][1] = Bs[buf][n0 + nt*8 + lr][kk + lc + 4];                \
            }                                                                   \
            _Pragma("unroll")                                                   \
            for (int mt = 0; mt < 4; mt++)                                      \
                _Pragma("unroll")                                               \
                for (int nt = 0; nt < 4; nt++)                                  \
                    mma_tf32(acc[mt][nt][0], acc[mt][nt][1],                    \
                             acc[mt][nt][2], acc[mt][nt][3],                    \
                             a[mt][0], a[mt][1], a[mt][2], a[mt][3],            \
                             b[nt][0], b[nt][1]);                               \
        }                                                                       \
    } while (0)

    PREF(0);
    STORE(0);
    __syncthreads();

    int nk = K / 16;
    for (int t = 0; t < nk; t++) {
        if (t + 1 < nk) PREF((t + 1) * 16);
        COMPUTE(t & 1);
        if (t + 1 < nk) STORE((t + 1) & 1);
        __syncthreads();
    }
#undef PREF
#undef STORE
#undef COMPUTE

    // epilogue: c0 at (row, col), c1 (row, col+1), c2 (row+8, col), c3 (row+8, col+1)
#pragma unroll
    for (int mt = 0; mt < 4; mt++) {
#pragma unroll
        for (int nt = 0; nt < 4; nt++) {
            int row = bm + m0 + mt * 16 + lr;
            int col = bn + n0 + nt * 8 + lc * 2;
            if (row < M) {
                float2 v = make_float2(acc[mt][nt][0], acc[mt][nt][1]);
                if (Res) {
                    const float2 rv = *reinterpret_cast<const float2*>(Res + (size_t)(base + row) * N + col);
                    v.x += rv.x; v.y += rv.y;
                }
                *reinterpret_cast<float2*>(C + (size_t)(base + row) * N + col) = v;
            }
            if (row + 8 < M) {
                float2 v = make_float2(acc[mt][nt][2], acc[mt][nt][3]);
                if (Res) {
                    const float2 rv = *reinterpret_cast<const float2*>(Res + (size_t)(base + row + 8) * N + col);
                    v.x += rv.x; v.y += rv.y;
                }
                *reinterpret_cast<float2*>(C + (size_t)(base + row + 8) * N + col) = v;
            }
        }
    }
}

// ---------------- small kernels ----------------
__global__ void reset_kernel(int* cnt) {
    if (threadIdx.x < E_) cnt[threadIdx.x] = 0;
}

__global__ void rmsnorm_kernel(const float* __restrict__ x, const float* __restrict__ w,
                               float* __restrict__ out) {
    int row = blockIdx.x;
    const float* xr = x + (size_t)row * D_;
    float ss = 0.f;
    for (int i = threadIdx.x; i < D_; i += 256) { float v = xr[i]; ss += v * v; }
    __shared__ float red[256];
    red[threadIdx.x] = ss; __syncthreads();
    for (int s = 128; s > 0; s >>= 1) {
        if (threadIdx.x < s) red[threadIdx.x] += red[threadIdx.x + s];
        __syncthreads();
    }
    float inv = rsqrtf(red[0] / (float)D_ + EPS_);
    float* orow = out + (size_t)row * D_;
    for (int i = threadIdx.x; i < D_; i += 256) orow[i] = xr[i] * inv * w[i];
}

__global__ void rope_kernel(float* __restrict__ x, const float* __restrict__ cosT,
                            const float* __restrict__ sinT, int nheads, int total) {
    int idx = blockIdx.x * blockDim.x + threadIdx.x;
    if (idx >= total) return;
    int p = idx & 63;
    int s = (idx / (64 * nheads)) % S_;
    float c = cosT[s * 64 + p];
    float sn = sinT[s * 64 + p];
    float x1 = x[2 * idx], x2 = x[2 * idx + 1];
    x[2 * idx]     = x1 * c - x2 * sn;
    x[2 * idx + 1] = x1 * sn + x2 * c;
}

// ---------------- small SGEMM: 64x64 tile, expert-batched (LoRA path) ----------------
__global__ void gemm_small(const float* __restrict__ A, const float* __restrict__ Bw,
                           float* __restrict__ C, int N, int K,
                           const int* __restrict__ tokIdx, int gatherA,
                           const float* __restrict__ Res,
                           float alpha, int accumulate,
                           const int* __restrict__ Mcnt, const int* __restrict__ Moff,
                           size_t strideB) {
    int z = blockIdx.z;
    int M = Mcnt[z];
    int bm = blockIdx.y * 64;
    if (bm >= M) return;
    int bn = blockIdx.x * 64;
    int base = Moff[z];
    const int* tok = tokIdx + z * T_;
    const float* Bz = Bw + (size_t)z * strideB;

    __shared__ float As[16][64];
    __shared__ float Bs[16][64];
    int tid = threadIdx.x;
    int tx = tid & 15, ty = tid >> 4;
    float acc[4][4];
#pragma unroll
    for (int i = 0; i < 4; i++)
#pragma unroll
        for (int j = 0; j < 4; j++) acc[i][j] = 0.f;

    for (int k0 = 0; k0 < K; k0 += 16) {
#pragma unroll
        for (int l = 0; l < 4; l++) {
            int ii = l * 256 + tid;
            int m = ii >> 4, kk = ii & 15;
            int row = bm + m;
            float a = 0.f;
            if (row < M) {
                int ar = gatherA ? tok[row] : base + row;
                a = A[(size_t)ar * K + k0 + kk];
            }
            As[kk][m] = a;
            float bv = 0.f;
            if (bn + m < N) bv = Bz[(size_t)(bn + m) * K + k0 + kk];
            Bs[kk][m] = bv;
        }
        __syncthreads();
#pragma unroll
        for (int kk = 0; kk < 16; kk++) {
            float4 av = *reinterpret_cast<const float4*>(&As[kk][ty * 4]);
            float4 bv = *reinterpret_cast<const float4*>(&Bs[kk][tx * 4]);
            float a0 = av.x, a1 = av.y, a2 = av.z, a3 = av.w;
            float b0 = bv.x, b1 = bv.y, b2 = bv.z, b3 = bv.w;
            acc[0][0] += a0*b0; acc[0][1] += a0*b1; acc[0][2] += a0*b2; acc[0][3] += a0*b3;
            acc[1][0] += a1*b0; acc[1][1] += a1*b1; acc[1][2] += a1*b2; acc[1][3] += a1*b3;
            acc[2][0] += a2*b0; acc[2][1] += a2*b1; acc[2][2] += a2*b2; acc[2][3] += a2*b3;
            acc[3][0] += a3*b0; acc[3][1] += a3*b1; acc[3][2] += a3*b2; acc[3][3] += a3*b3;
        }
        __syncthreads();
    }
#pragma unroll
    for (int i = 0; i < 4; i++) {
        int row = bm + ty * 4 + i;
        if (row >= M) continue;
        size_t crow = (size_t)(base + row) * N;
#pragma unroll
        for (int j = 0; j < 4; j++) {
            int col = bn + tx * 4 + j;
            if (col >= N) continue;
            float val = alpha * acc[i][j];
            if (Res) val += Res[(size_t)tok[row] * N + col];
            if (accumulate) C[crow + col] += val;
            else            C[crow + col] = val;
        }
    }
}

// ---------------- flash attention, fp32, 64-query tiles ----------------
#define ATTN_SMEM (20928 * 4)
__global__ void attn_kernel(const float* __restrict__ q, const float* __restrict__ k,
                            const float* __restrict__ v, const float* __restrict__ mask,
                            float* __restrict__ o) {
    extern __shared__ float smf[];
    float* Qt   = smf;
    float* KV   = smf + 8320;
    float* Sc   = smf + 16640;
    float* mrow = smf + 20800;
    float* lrow = smf + 20864;

    int qt = blockIdx.x, h = blockIdx.y, b = blockIdx.z;
    int hkv = h >> 1;
    int tid = threadIdx.x;
    int q0 = qt * 64;

    for (int i = tid; i < 64 * 128; i += 256) {
        int r = i >> 7, d = i & 127;
        Qt[d * 65 + r] = q[(((size_t)b * S_ + q0 + r) * H_ + h) * HD_ + d];
    }
    if (tid < 64) { mrow[tid] = -3e38f; lrow[tid] = 0.f; }
    float acc[32];
#pragma unroll
    for (int i = 0; i < 32; i++) acc[i] = 0.f;
    int tx = tid & 15, ty = tid >> 4;
    int rg = tid >> 2, cg = tid & 3;
    __syncthreads();

    const float sca = 0.08838834764831845f;
    for (int kt = 0; kt < S_; kt += 64) {
        for (int i = tid; i < 64 * 128; i += 256) {
            int r = i >> 7, d = i & 127;
            KV[d * 65 + r] = k[(((size_t)b * S_ + kt + r) * HKV_ + hkv) * HD_ + d];
        }
        __syncthreads();
        float sc[4][4];
#pragma unroll
        for (int i = 0; i < 4; i++)
#pragma unroll
            for (int j = 0; j < 4; j++) sc[i][j] = 0.f;
        for (int d = 0; d < 128; d++) {
            float a0 = Qt[d * 65 + ty * 4 + 0];
            float a1 = Qt[d * 65 + ty * 4 + 1];
            float a2 = Qt[d * 65 + ty * 4 + 2];
            float a3 = Qt[d * 65 + ty * 4 + 3];
            float b0 = KV[d * 65 + tx * 4 + 0];
            float b1 = KV[d * 65 + tx * 4 + 1];
            float b2 = KV[d * 65 + tx * 4 + 2];
            float b3 = KV[d * 65 + tx * 4 + 3];
            sc[0][0] += a0*b0; sc[0][1] += a0*b1; sc[0][2] += a0*b2; sc[0][3] += a0*b3;
            sc[1][0] += a1*b0; sc[1][1] += a1*b1; sc[1][2] += a1*b2; sc[1][3] += a1*b3;
            sc[2][0] += a2*b0; sc[2][1] += a2*b1; sc[2][2] += a2*b2; sc[2][3] += a2*b3;
            sc[3][0] += a3*b0; sc[3][1] += a3*b1; sc[3][2] += a3*b2; sc[3][3] += a3*b3;
        }
#pragma unroll
        for (int i = 0; i < 4; i++)
#pragma unroll
            for (int j = 0; j < 4; j++) {
                int rr = ty * 4 + i, cc = tx * 4 + j;
                Sc[rr * 65 + cc] = sc[i][j] * sca + mask[(q0 + rr) * S_ + kt + cc];
            }
        __syncthreads();
        for (int i = tid; i < 64 * 128; i += 256) {
            int r = i >> 7, d = i & 127;
            KV[r * 128 + d] = v[(((size_t)b * S_ + kt + r) * HKV_ + hkv) * HD_ + d];
        }
        float tm = -3e38f;
#pragma unroll
        for (int ii = 0; ii < 16; ii++) tm = fmaxf(tm, Sc[rg * 65 + cg + 4 * ii]);
        tm = fmaxf(tm, __shfl_xor_sync(0xffffffffu, tm, 1));
        tm = fmaxf(tm, __shfl_xor_sync(0xffffffffu, tm, 2));
        float mprev = mrow[rg];
        float mnew = fmaxf(mprev, tm);
        float fac = expf(mprev - mnew);
        float ls = 0.f;
#pragma unroll
        for (int ii = 0; ii < 16; ii++) {
            float p = expf(Sc[rg * 65 + cg + 4 * ii] - mnew);
            Sc[rg * 65 + cg + 4 * ii] = p;
            ls += p;
        }
        ls += __shfl_xor_sync(0xffffffffu, ls, 1);
        ls += __shfl_xor_sync(0xffffffffu, ls, 2);
        if (cg == 0) { mrow[rg] = mnew; lrow[rg] = lrow[rg] * fac + ls; }
#pragma unroll
        for (int ii = 0; ii < 32; ii++) acc[ii] *= fac;
        __syncthreads();
        for (int j = 0; j < 64; j++) {
            float p = Sc[rg * 65 + j];
#pragma unroll
            for (int ii = 0; ii < 32; ii++) acc[ii] += p * KV[j * 128 + cg + 4 * ii];
        }
        __syncthreads();
    }
    float invl = 1.f / lrow[rg];
#pragma unroll
    for (int ii = 0; ii < 32; ii++)
        o[(((size_t)b * S_ + q0 + rg) * H_ + h) * HD_ + cg + 4 * ii] = acc[ii] * invl;
}

// ---------------- router ----------------
__global__ void router_logits_kernel(const float* __restrict__ sn, const float* __restrict__ gw,
                                     float* __restrict__ logits) {
    int t = blockIdx.x;
    float part[E_];
#pragma unroll
    for (int e = 0; e < E_; e++) part[e] = 0.f;
    const float* x = sn + (size_t)t * D_;
    for (int kk = threadIdx.x; kk < D_; kk += 256) {
        float xv = x[kk];
#pragma unroll
        for (int e = 0; e < E_; e++) part[e] += xv * gw[(size_t)e * D_ + kk];
    }
    __shared__ float red[256];
    for (int e = 0; e < E_; e++) {
        red[threadIdx.x] = part[e]; __syncthreads();
        for (int s = 128; s > 0; s >>= 1) {
            if (threadIdx.x < s) red[threadIdx.x] += red[threadIdx.x + s];
            __syncthreads();
        }
        if (threadIdx.x == 0) logits[(size_t)t * E_ + e] = red[0];
        __syncthreads();
    }
}

__global__ void col_softmax_stats(const float* __restrict__ logits, float* __restrict__ zmax,
                                  float* __restrict__ zsum) {
    int be = blockIdx.x;
    int b = be / E_, e = be % E_;
    __shared__ float red[256];
    float mx = -3e38f;
    for (int s = threadIdx.x; s < S_; s += 256)
        mx = fmaxf(mx, logits[((size_t)b * S_ + s) * E_ + e]);
    red[threadIdx.x] = mx; __syncthreads();
    for (int s = 128; s > 0; s >>= 1) {
        if (threadIdx.x < s) red[threadIdx.x] = fmaxf(red[threadIdx.x], red[threadIdx.x + s]);
        __syncthreads();
    }
    mx = red[0]; __syncthreads();
    float sum = 0.f;
    for (int s = threadIdx.x; s < S_; s += 256)
        sum += expf(logits[((size_t)b * S_ + s) * E_ + e] - mx);
    red[threadIdx.x] = sum; __syncthreads();
    for (int s = 128; s > 0; s >>= 1) {
        if (threadIdx.x < s) red[threadIdx.x] += red[threadIdx.x + s];
        __syncthreads();
    }
    if (threadIdx.x == 0) { zmax[be] = mx; zsum[be] = red[0]; }
}

__global__ void top2_kernel(const float* __restrict__ logits, const float* __restrict__ zmax,
                            const float* __restrict__ zsum, int* __restrict__ cnt,
                            int* __restrict__ tok, int* __restrict__ sel,
                            int* __restrict__ pos, float* __restrict__ wgt) {
    int t = blockIdx.x * blockDim.x + threadIdx.x;
    if (t >= T_) return;
    int b = t / S_;
    float rw[E_];
#pragma unroll
    for (int e = 0; e < E_; e++)
        rw[e] = expf(logits[(size_t)t * E_ + e] - zmax[b * E_ + e]) / zsum[b * E_ + e];
    int e0 = 0; float v0 = rw[0];
#pragma unroll
    for (int e = 1; e < E_; e++) if (rw[e] > v0) { v0 = rw[e]; e0 = e; }
    int e1 = -1; float v1 = -3e38f;
#pragma unroll
    for (int e = 0; e < E_; e++) if (e != e0 && rw[e] > v1) { v1 = rw[e]; e1 = e; }
    float inv = 1.f / (v0 + v1);
    int p0 = atomicAdd(&cnt[e0], 1);
    tok[e0 * T_ + p0] = t;
    int p1 = atomicAdd(&cnt[e1], 1);
    tok[e1 * T_ + p1] = t;
    sel[2*t] = e0; pos[2*t] = p0; wgt[2*t] = v0 * inv;
    sel[2*t+1] = e1; pos[2*t+1] = p1; wgt[2*t+1] = v1 * inv;
}

__global__ void offsets_kernel(const int* __restrict__ cnt, int* __restrict__ off) {
    if (threadIdx.x == 0) {
        int s = 0;
        for (int e = 0; e < E_; e++) { off[e] = s; s += cnt[e]; }
    }
}

__global__ void silu_kernel(float* __restrict__ h1, const float* __restrict__ h3,
                            const int* __restrict__ cnt, const int* __restrict__ off) {
    int z = blockIdx.y;
    int row = blockIdx.x;
    if (row >= cnt[z]) return;
    size_t g = (size_t)(off[z] + row) * F_;
    for (int i = threadIdx.x; i < F_; i += 256) {
        float x = h1[g + i];
        h1[g + i] = (x / (1.f + expf(-x))) * h3[g + i];
    }
}

__global__ void gather_kernel(const float* __restrict__ expout, const int* __restrict__ off,
                              const int* __restrict__ sel, const int* __restrict__ pos,
                              const float* __restrict__ wgt, float* __restrict__ out) {
    int t = blockIdx.x;
    int e0 = sel[2*t], e1 = sel[2*t+1];
    size_t r0 = (size_t)(off[e0] + pos[2*t]) * D_;
    size_t r1 = (size_t)(off[e1] + pos[2*t+1]) * D_;
    float w0 = wgt[2*t], w1 = wgt[2*t+1];
    for (int i = threadIdx.x; i < D_; i += 256)
        out[(size_t)t * D_ + i] += w0 * expout[r0 + i] + w1 * expout[r1 + i];
}

// ---------------- host launch ----------------
extern "C" void kernel_launch(void* const* d_in, const int* in_sizes, int n_in,
                              void* d_out, int out_size) {
    const float* data   = (const float*)d_in[0];
    const float* mask   = (const float*)d_in[1];
    const float* ropec  = (const float*)d_in[2];
    const float* ropes  = (const float*)d_in[3];
    const float* anw    = (const float*)d_in[4];
    const float* fnw    = (const float*)d_in[5];
    const float* wq     = (const float*)d_in[6];
    const float* wk     = (const float*)d_in[7];
    const float* wv     = (const float*)d_in[8];
    const float* wo     = (const float*)d_in[9];
    const float* gate_w = (const float*)d_in[10];
    const float* w1     = (const float*)d_in[11];
    const float* w2     = (const float*)d_in[12];
    const float* w3     = (const float*)d_in[13];
    const float* w1_a   = (const float*)d_in[14];
    const float* w1_b   = (const float*)d_in[15];
    const float* w3_a   = (const float*)d_in[16];
    const float* w3_b   = (const float*)d_in[17];
    const float* w2_a   = (const float*)d_in[18];
    const float* w2_b   = (const float*)d_in[19];
    float* out = (float*)d_out;

    float *xn, *qb, *kb, *vb, *attn, *sn, *c1, *c3, *h1, *h3, *u1, *u3, *u2;
    float *logits, *zmax, *zsum, *wgt, *expout;
    int *cnt, *off, *tok, *sel, *pos;
    cudaGetSymbolAddress((void**)&xn, g_xn);
    cudaGetSymbolAddress((void**)&qb, g_q);
    cudaGetSymbolAddress((void**)&kb, g_k);
    cudaGetSymbolAddress((void**)&vb, g_v);
    cudaGetSymbolAddress((void**)&attn, g_attn);
    cudaGetSymbolAddress((void**)&sn, g_sn);
    cudaGetSymbolAddress((void**)&c1, g_c1);
    cudaGetSymbolAddress((void**)&c3, g_c3);
    cudaGetSymbolAddress((void**)&h1, g_h1);
    cudaGetSymbolAddress((void**)&h3, g_h3);
    cudaGetSymbolAddress((void**)&u1, g_u1);
    cudaGetSymbolAddress((void**)&u3, g_u3);
    cudaGetSymbolAddress((void**)&u2, g_u2);
    cudaGetSymbolAddress((void**)&expout, g_expout);
    cudaGetSymbolAddress((void**)&logits, g_logits);
    cudaGetSymbolAddress((void**)&zmax, g_zmax);
    cudaGetSymbolAddress((void**)&zsum, g_zsum);
    cudaGetSymbolAddress((void**)&cnt, g_cnt);
    cudaGetSymbolAddress((void**)&off, g_off);
    cudaGetSymbolAddress((void**)&tok, g_tok);
    cudaGetSymbolAddress((void**)&sel, g_sel);
    cudaGetSymbolAddress((void**)&pos, g_pos);
    cudaGetSymbolAddress((void**)&wgt, g_wgt);

    cudaFuncSetAttribute(attn_kernel, cudaFuncAttributeMaxDynamicSharedMemorySize, ATTN_SMEM);

    reset_kernel<<<1, 32>>>(cnt);
    rmsnorm_kernel<<<T_, 256>>>(data, anw, xn);

    // QKV projections (tf32 mma)
    gemm_mma<<<dim3(D_/128, T_/128, 1), 256>>>(xn, wq, qb, T_, D_, D_,
        nullptr, nullptr, nullptr);
    gemm_mma<<<dim3((HKV_*HD_)/128, T_/128, 1), 256>>>(xn, wk, kb, T_, HKV_*HD_, D_,
        nullptr, nullptr, nullptr);
    gemm_mma<<<dim3((HKV_*HD_)/128, T_/128, 1), 256>>>(xn, wv, vb, T_, HKV_*HD_, D_,
        nullptr, nullptr, nullptr);

    rope_kernel<<<(T_*H_*64 + 255)/256, 256>>>(qb, ropec, ropes, H_, T_*H_*64);
    rope_kernel<<<(T_*HKV_*64 + 255)/256, 256>>>(kb, ropec, ropes, HKV_, T_*HKV_*64);

    attn_kernel<<<dim3(S_/64, H_, B_), 256, ATTN_SMEM>>>(qb, kb, vb, mask, attn);

    // out = data + attn @ wo^T
    gemm_mma<<<dim3(D_/128, T_/128, 1), 256>>>(attn, wo, out, T_, D_, D_,
        data, nullptr, nullptr);

    rmsnorm_kernel<<<T_, 256>>>(out, fnw, sn);

    router_logits_kernel<<<T_, 256>>>(sn, gate_w, logits);
    col_softmax_stats<<<B_*E_, 256>>>(logits, zmax, zsum);
    top2_kernel<<<T_/256, 256>>>(logits, zmax, zsum, cnt, tok, sel, pos, wgt);
    offsets_kernel<<<1, 32>>>(cnt, off);

    // dense c1/c3 (tf32 mma)
    gemm_mma<<<dim3(F_/128, T_/128, 1), 256>>>(sn, w1, c1, T_, F_, D_,
        nullptr, nullptr, nullptr);
    gemm_mma<<<dim3(F_/128, T_/128, 1), 256>>>(sn, w3, c3, T_, F_, D_,
        nullptr, nullptr, nullptr);

    // ---- expert-batched LoRA path (z = expert) ----
    gemm_small<<<dim3(1, T_/64, E_), 256>>>(sn, w1_a, u1, R_, D_,
        tok, 1, nullptr, 1.f, 0, cnt, off, (size_t)R_*D_);
    gemm_small<<<dim3(F_/64, T_/64, E_), 256>>>(u1, w1_b, h1, F_, R_,
        tok, 0, c1, SCALE_, 0, cnt, off, (size_t)F_*R_);
    gemm_small<<<dim3(1, T_/64, E_), 256>>>(sn, w3_a, u3, R_, D_,
        tok, 1, nullptr, 1.f, 0, cnt, off, (size_t)R_*D_);
    gemm_small<<<dim3(F_/64, T_/64, E_), 256>>>(u3, w3_b, h3, F_, R_,
        tok, 0, c3, SCALE_, 0, cnt, off, (size_t)F_*R_);
    silu_kernel<<<dim3(T_, E_), 256>>>(h1, h3, cnt, off);
    gemm_small<<<dim3(1, T_/64, E_), 256>>>(h1, w2_a, u2, R_, F_,
        tok, 0, nullptr, 1.f, 0, cnt, off, (size_t)R_*F_);
    // expout = sr @ w2^T  (tf32 mma, expert-batched with dynamic M)
    gemm_mma<<<dim3(D_/128, T_/128, E_), 256>>>(h1, w2, expout, T_, D_, F_,
        nullptr, cnt, off);
    // expout += SCALE * u2 @ w2_b^T
    gemm_small<<<dim3(D_/64, T_/64, E_), 256>>>(u2, w2_b, expout, D_, R_,
        tok, 0, nullptr, SCALE_, 1, cnt, off, (size_t)D_*R_);

    // out[t] += w0*expout[slot0] + w1*expout[slot1]
    gather_kernel<<<T_, 256>>>(expout, off, sel, pos, wgt, out);
}

// round 10
// speedup vs baseline: 5.3720x; 1.0151x over previous
#include <cuda_runtime.h>
#include <math.h>
#include <stdint.h>

#define B_ 2
#define S_ 1024
#define D_ 2048
#define H_ 16
#define HKV_ 8
#define HD_ 128
#define F_ 5632
#define E_ 8
#define R_ 16
#define T_ (B_*S_)
#define EPS_ 1e-5f
#define SCALE_ 2.0f

// ---------------- device scratch (static, allocation-free) ----------------
__device__ float g_xn[T_*D_];
__device__ float g_q[T_*D_];
__device__ float g_k[T_*HKV_*HD_];
__device__ float g_v[T_*HKV_*HD_];
__device__ float g_attn[T_*D_];
__device__ float g_sn[T_*D_];
__device__ float g_c1[T_*F_];
__device__ float g_c3[T_*F_];
__device__ float g_h1[2*T_*F_];
__device__ float g_h3[2*T_*F_];
__device__ float g_expout[2*T_*D_];
__device__ float g_u1[2*T_*R_];
__device__ float g_u3[2*T_*R_];
__device__ float g_u2[2*T_*R_];
__device__ float g_logits[T_*E_];
__device__ float g_zmax[B_*E_];
__device__ float g_zsum[B_*E_];
__device__ int   g_cnt[E_];
__device__ int   g_off[E_];
__device__ int   g_tok[E_*T_];
__device__ int   g_sel[2*T_];
__device__ int   g_pos[2*T_];
__device__ float g_wgt[2*T_];

// ---------------- helpers ----------------
__device__ __forceinline__ float tf32r(float x) {
    uint32_t y;
    asm("cvt.rna.tf32.f32 %0, %1;" : "=r"(y) : "f"(x));
    return __uint_as_float(y);
}
__device__ __forceinline__ void mma_tf32(float& d0, float& d1, float& d2, float& d3,
                                         float a0, float a1, float a2, float a3,
                                         float b0, float b1) {
    asm volatile(
        "mma.sync.aligned.m16n8k8.row.col.f32.tf32.tf32.f32 "
        "{%0,%1,%2,%3}, {%4,%5,%6,%7}, {%8,%9}, {%0,%1,%2,%3};"
        : "+f"(d0), "+f"(d1), "+f"(d2), "+f"(d3)
        : "r"(__float_as_uint(a0)), "r"(__float_as_uint(a1)),
          "r"(__float_as_uint(a2)), "r"(__float_as_uint(a3)),
          "r"(__float_as_uint(b0)), "r"(__float_as_uint(b1)));
}

// ---------------- tf32 mma.sync GEMM v2: 128x256 CTA tile, 64x64 warp tile ----------------
// Dynamic smem: As[2][128][20] + Bs[2][256][20] = 61440 bytes
#define GEMM_SMEM ((2*128*20 + 2*256*20) * 4)
__global__ __launch_bounds__(256, 1)
void gemm_mma(const float* __restrict__ A, const float* __restrict__ Bw,
              float* __restrict__ C, int M, int N, int K,
              const float* __restrict__ Res,
              const int* __restrict__ Mcnt, const int* __restrict__ Moff,
              const float* __restrict__ ropec, const float* __restrict__ ropes) {
    extern __shared__ float smdyn[];
    typedef float (*AsT)[128][20];
    typedef float (*BsT)[256][20];
    AsT As = reinterpret_cast<AsT>(smdyn);                 // [2][128][20]
    BsT Bs = reinterpret_cast<BsT>(smdyn + 2 * 128 * 20);  // [2][256][20]

    int z = blockIdx.z;
    if (Mcnt) M = Mcnt[z];
    int bm = blockIdx.y * 128;
    if (bm >= M) return;
    int bn = blockIdx.x * 256;
    int base = Moff ? Moff[z] : 0;

    int tid = threadIdx.x, wid = tid >> 5, lid = tid & 31;
    int wm = wid >> 2, wn = wid & 3;           // 2 x 4 warp grid, 64x64 tiles
    int m0 = wm * 64, n0 = wn * 64;
    int lr = lid >> 2, lc = lid & 3;

    float acc[4][8][4];
#pragma unroll
    for (int i = 0; i < 4; i++)
#pragma unroll
        for (int j = 0; j < 8; j++)
#pragma unroll
            for (int q = 0; q < 4; q++) acc[i][j][q] = 0.f;

    int grA = tid >> 2;                        // 0..63
    int gc  = (tid & 3) * 4;

    float4 pa[2], pb[4];
    const float4 z4 = make_float4(0.f, 0.f, 0.f, 0.f);

#define PREF(k0) do {                                                           \
        _Pragma("unroll")                                                       \
        for (int it = 0; it < 2; it++) {                                        \
            int gr = it * 64 + grA;                                             \
            pa[it] = z4;                                                        \
            if (bm + gr < M)                                                    \
                pa[it] = *reinterpret_cast<const float4*>(                      \
                    A + (size_t)(base + bm + gr) * K + (k0) + gc);              \
        }                                                                       \
        _Pragma("unroll")                                                       \
        for (int it = 0; it < 4; it++) {                                        \
            int gr = it * 64 + grA;                                             \
            pb[it] = *reinterpret_cast<const float4*>(                          \
                    Bw + (size_t)(bn + gr) * K + (k0) + gc);                    \
        }                                                                       \
    } while (0)

#define STOREM(buf) do {                                                        \
        _Pragma("unroll")                                                       \
        for (int it = 0; it < 2; it++) {                                        \
            int gr = it * 64 + grA;                                             \
            As[buf][gr][gc + 0] = tf32r(pa[it].x);                              \
            As[buf][gr][gc + 1] = tf32r(pa[it].y);                              \
            As[buf][gr][gc + 2] = tf32r(pa[it].z);                              \
            As[buf][gr][gc + 3] = tf32r(pa[it].w);                              \
        }                                                                       \
        _Pragma("unroll")                                                       \
        for (int it = 0; it < 4; it++) {                                        \
            int gr = it * 64 + grA;                                             \
            Bs[buf][gr][gc + 0] = tf32r(pb[it].x);                              \
            Bs[buf][gr][gc + 1] = tf32r(pb[it].y);                              \
            Bs[buf][gr][gc + 2] = tf32r(pb[it].z);                              \
            Bs[buf][gr][gc + 3] = tf32r(pb[it].w);                              \
        }                                                                       \
    } while (0)

#define COMPUTE(buf) do {                                                       \
        _Pragma("unroll")                                                       \
        for (int ks = 0; ks < 2; ks++) {                                        \
            int kk = ks * 8;                                                    \
            float a[4][4], b[8][2];                                             \
            _Pragma("unroll")                                                   \
            for (int mt = 0; mt < 4; mt++) {                                    \
                a[mt][0] = As[buf][m0 + mt*16 + lr][kk + lc];                   \
                a[mt][1] = As[buf][m0 + mt*16 + lr + 8][kk + lc];               \
                a[mt][2] = As[buf][m0 + mt*16 + lr][kk + lc + 4];               \
                a[mt][3] = As[buf][m0 + mt*16 + lr + 8][kk + lc + 4];           \
            }                                                                   \
            _Pragma("unroll")                                                   \
            for (int nt = 0; nt < 8; nt++) {                                    \
                b[nt][0] = Bs[buf][n0 + nt*8 + lr][kk + lc];                    \
                b[nt][1] = Bs[buf][n0 + nt*8 + lr][kk + lc + 4];                \
            }                                                                   \
            _Pragma("unroll")                                                   \
            for (int mt = 0; mt < 4; mt++)                                      \
                _Pragma("unroll")                                               \
                for (int nt = 0; nt < 8; nt++)                                  \
                    mma_tf32(acc[mt][nt][0], acc[mt][nt][1],                    \
                             acc[mt][nt][2], acc[mt][nt][3],                    \
                             a[mt][0], a[mt][1], a[mt][2], a[mt][3],            \
                             b[nt][0], b[nt][1]);                               \
        }                                                                       \
    } while (0)

    PREF(0);
    STOREM(0);
    __syncthreads();

    int nk = K / 16;
    for (int t = 0; t < nk; t++) {
        if (t + 1 < nk) PREF((t + 1) * 16);
        COMPUTE(t & 1);
        if (t + 1 < nk) STOREM((t + 1) & 1);
        __syncthreads();
    }
#undef PREF
#undef STOREM
#undef COMPUTE

    // epilogue: per (mt, nt): rows (row, row+8), cols (col, col+1)
#pragma unroll
    for (int mt = 0; mt < 4; mt++) {
#pragma unroll
        for (int nt = 0; nt < 8; nt++) {
            int row = bm + m0 + mt * 16 + lr;
            int col = bn + n0 + nt * 8 + lc * 2;
#pragma unroll
            for (int hh = 0; hh < 2; hh++) {
                int r = row + hh * 8;
                if (r >= M) continue;
                float2 v = make_float2(acc[mt][nt][hh * 2], acc[mt][nt][hh * 2 + 1]);
                if (Res) {
                    const float2 rv = *reinterpret_cast<const float2*>(
                        Res + (size_t)(base + r) * N + col);
                    v.x += rv.x; v.y += rv.y;
                }
                if (ropec) {
                    int p = (col & 127) >> 1;
                    int sp = (base + r) & (S_ - 1);
                    float cc = ropec[sp * 64 + p];
                    float ss = ropes[sp * 64 + p];
                    float o1 = v.x * cc - v.y * ss;
                    float o2 = v.x * ss + v.y * cc;
                    v.x = o1; v.y = o2;
                }
                *reinterpret_cast<float2*>(C + (size_t)(base + r) * N + col) = v;
            }
        }
    }
}

// ---------------- small kernels ----------------
__global__ void reset_kernel(int* cnt) {
    if (threadIdx.x < E_) cnt[threadIdx.x] = 0;
}

__global__ void rmsnorm_kernel(const float* __restrict__ x, const float* __restrict__ w,
                               float* __restrict__ out) {
    int row = blockIdx.x;
    const float* xr = x + (size_t)row * D_;
    float ss = 0.f;
    for (int i = threadIdx.x; i < D_; i += 256) { float v = xr[i]; ss += v * v; }
    __shared__ float red[256];
    red[threadIdx.x] = ss; __syncthreads();
    for (int s = 128; s > 0; s >>= 1) {
        if (threadIdx.x < s) red[threadIdx.x] += red[threadIdx.x + s];
        __syncthreads();
    }
    float inv = rsqrtf(red[0] / (float)D_ + EPS_);
    float* orow = out + (size_t)row * D_;
    for (int i = threadIdx.x; i < D_; i += 256) orow[i] = xr[i] * inv * w[i];
}

// ---------------- small SGEMM: 64x64 tile, expert-batched (LoRA path) ----------------
// siluMul: if non-null, out = silu(val) * siluMul[crow+col]
__global__ void gemm_small(const float* __restrict__ A, const float* __restrict__ Bw,
                           float* __restrict__ C, int N, int K,
                           const int* __restrict__ tokIdx, int gatherA,
                           const float* __restrict__ Res,
                           float alpha, int accumulate,
                           const int* __restrict__ Mcnt, const int* __restrict__ Moff,
                           size_t strideB, const float* __restrict__ siluMul) {
    int z = blockIdx.z;
    int M = Mcnt[z];
    int bm = blockIdx.y * 64;
    if (bm >= M) return;
    int bn = blockIdx.x * 64;
    int base = Moff[z];
    const int* tok = tokIdx + z * T_;
    const float* Bz = Bw + (size_t)z * strideB;

    __shared__ float As[16][64];
    __shared__ float Bs[16][64];
    int tid = threadIdx.x;
    int tx = tid & 15, ty = tid >> 4;
    float acc[4][4];
#pragma unroll
    for (int i = 0; i < 4; i++)
#pragma unroll
        for (int j = 0; j < 4; j++) acc[i][j] = 0.f;

    for (int k0 = 0; k0 < K; k0 += 16) {
#pragma unroll
        for (int l = 0; l < 4; l++) {
            int ii = l * 256 + tid;
            int m = ii >> 4, kk = ii & 15;
            int row = bm + m;
            float a = 0.f;
            if (row < M) {
                int ar = gatherA ? tok[row] : base + row;
                a = A[(size_t)ar * K + k0 + kk];
            }
            As[kk][m] = a;
            float bv = 0.f;
            if (bn + m < N) bv = Bz[(size_t)(bn + m) * K + k0 + kk];
            Bs[kk][m] = bv;
        }
        __syncthreads();
#pragma unroll
        for (int kk = 0; kk < 16; kk++) {
            float4 av = *reinterpret_cast<const float4*>(&As[kk][ty * 4]);
            float4 bv = *reinterpret_cast<const float4*>(&Bs[kk][tx * 4]);
            float a0 = av.x, a1 = av.y, a2 = av.z, a3 = av.w;
            float b0 = bv.x, b1 = bv.y, b2 = bv.z, b3 = bv.w;
            acc[0][0] += a0*b0; acc[0][1] += a0*b1; acc[0][2] += a0*b2; acc[0][3] += a0*b3;
            acc[1][0] += a1*b0; acc[1][1] += a1*b1; acc[1][2] += a1*b2; acc[1][3] += a1*b3;
            acc[2][0] += a2*b0; acc[2][1] += a2*b1; acc[2][2] += a2*b2; acc[2][3] += a2*b3;
            acc[3][0] += a3*b0; acc[3][1] += a3*b1; acc[3][2] += a3*b2; acc[3][3] += a3*b3;
        }
        __syncthreads();
    }
#pragma unroll
    for (int i = 0; i < 4; i++) {
        int row = bm + ty * 4 + i;
        if (row >= M) continue;
        size_t crow = (size_t)(base + row) * N;
#pragma unroll
        for (int j = 0; j < 4; j++) {
            int col = bn + tx * 4 + j;
            if (col >= N) continue;
            float val = alpha * acc[i][j];
            if (Res) val += Res[(size_t)tok[row] * N + col];
            if (siluMul) {
                float s = val / (1.f + expf(-val));
                val = s * siluMul[crow + col];
            }
            if (accumulate) C[crow + col] += val;
            else            C[crow + col] = val;
        }
    }
}

// ---------------- flash attention, fp32, 64-query tiles ----------------
#define ATTN_SMEM (20928 * 4)
__global__ void attn_kernel(const float* __restrict__ q, const float* __restrict__ k,
                            const float* __restrict__ v, const float* __restrict__ mask,
                            float* __restrict__ o) {
    extern __shared__ float smf[];
    float* Qt   = smf;
    float* KV   = smf + 8320;
    float* Sc   = smf + 16640;
    float* mrow = smf + 20800;
    float* lrow = smf + 20864;

    int qt = blockIdx.x, h = blockIdx.y, b = blockIdx.z;
    int hkv = h >> 1;
    int tid = threadIdx.x;
    int q0 = qt * 64;

    for (int i = tid; i < 64 * 128; i += 256) {
        int r = i >> 7, d = i & 127;
        Qt[d * 65 + r] = q[(((size_t)b * S_ + q0 + r) * H_ + h) * HD_ + d];
    }
    if (tid < 64) { mrow[tid] = -3e38f; lrow[tid] = 0.f; }
    float acc[32];
#pragma unroll
    for (int i = 0; i < 32; i++) acc[i] = 0.f;
    int tx = tid & 15, ty = tid >> 4;
    int rg = tid >> 2, cg = tid & 3;
    __syncthreads();

    const float sca = 0.08838834764831845f;
    for (int kt = 0; kt < S_; kt += 64) {
        for (int i = tid; i < 64 * 128; i += 256) {
            int r = i >> 7, d = i & 127;
            KV[d * 65 + r] = k[(((size_t)b * S_ + kt + r) * HKV_ + hkv) * HD_ + d];
        }
        __syncthreads();
        float sc[4][4];
#pragma unroll
        for (int i = 0; i < 4; i++)
#pragma unroll
            for (int j = 0; j < 4; j++) sc[i][j] = 0.f;
        for (int d = 0; d < 128; d++) {
            float a0 = Qt[d * 65 + ty * 4 + 0];
            float a1 = Qt[d * 65 + ty * 4 + 1];
            float a2 = Qt[d * 65 + ty * 4 + 2];
            float a3 = Qt[d * 65 + ty * 4 + 3];
            float b0 = KV[d * 65 + tx * 4 + 0];
            float b1 = KV[d * 65 + tx * 4 + 1];
            float b2 = KV[d * 65 + tx * 4 + 2];
            float b3 = KV[d * 65 + tx * 4 + 3];
            sc[0][0] += a0*b0; sc[0][1] += a0*b1; sc[0][2] += a0*b2; sc[0][3] += a0*b3;
            sc[1][0] += a1*b0; sc[1][1] += a1*b1; sc[1][2] += a1*b2; sc[1][3] += a1*b3;
            sc[2][0] += a2*b0; sc[2][1] += a2*b1; sc[2][2] += a2*b2; sc[2][3] += a2*b3;
            sc[3][0] += a3*b0; sc[3][1] += a3*b1; sc[3][2] += a3*b2; sc[3][3] += a3*b3;
        }
#pragma unroll
        for (int i = 0; i < 4; i++)
#pragma unroll
            for (int j = 0; j < 4; j++) {
                int rr = ty * 4 + i, cc = tx * 4 + j;
                Sc[rr * 65 + cc] = sc[i][j] * sca + mask[(q0 + rr) * S_ + kt + cc];
            }
        __syncthreads();
        for (int i = tid; i < 64 * 128; i += 256) {
            int r = i >> 7, d = i & 127;
            KV[r * 128 + d] = v[(((size_t)b * S_ + kt + r) * HKV_ + hkv) * HD_ + d];
        }
        float tm = -3e38f;
#pragma unroll
        for (int ii = 0; ii < 16; ii++) tm = fmaxf(tm, Sc[rg * 65 + cg + 4 * ii]);
        tm = fmaxf(tm, __shfl_xor_sync(0xffffffffu, tm, 1));
        tm = fmaxf(tm, __shfl_xor_sync(0xffffffffu, tm, 2));
        float mprev = mrow[rg];
        float mnew = fmaxf(mprev, tm);
        float fac = expf(mprev - mnew);
        float ls = 0.f;
#pragma unroll
        for (int ii = 0; ii < 16; ii++) {
            float p = expf(Sc[rg * 65 + cg + 4 * ii] - mnew);
            Sc[rg * 65 + cg + 4 * ii] = p;
            ls += p;
        }
        ls += __shfl_xor_sync(0xffffffffu, ls, 1);
        ls += __shfl_xor_sync(0xffffffffu, ls, 2);
        if (cg == 0) { mrow[rg] = mnew; lrow[rg] = lrow[rg] * fac + ls; }
#pragma unroll
        for (int ii = 0; ii < 32; ii++) acc[ii] *= fac;
        __syncthreads();
        for (int j = 0; j < 64; j++) {
            float p = Sc[rg * 65 + j];
#pragma unroll
            for (int ii = 0; ii < 32; ii++) acc[ii] += p * KV[j * 128 + cg + 4 * ii];
        }
        __syncthreads();
    }
    float invl = 1.f / lrow[rg];
#pragma unroll
    for (int ii = 0; ii < 32; ii++)
        o[(((size_t)b * S_ + q0 + rg) * H_ + h) * HD_ + cg + 4 * ii] = acc[ii] * invl;
}

// ---------------- router ----------------
__global__ void router_logits_kernel(const float* __restrict__ sn, const float* __restrict__ gw,
                                     float* __restrict__ logits) {
    int t = blockIdx.x;
    int wid = threadIdx.x >> 5, lid = threadIdx.x & 31;
    const float* x = sn + (size_t)t * D_;
    const float* g = gw + (size_t)wid * D_;
    float s = 0.f;
    for (int i = lid * 4; i < D_; i += 128) {
        float4 xv = *reinterpret_cast<const float4*>(x + i);
        float4 gv = *reinterpret_cast<const float4*>(g + i);
        s += xv.x * gv.x + xv.y * gv.y + xv.z * gv.z + xv.w * gv.w;
    }
#pragma unroll
    for (int o = 16; o > 0; o >>= 1) s += __shfl_xor_sync(0xffffffffu, s, o);
    if (lid == 0) logits[(size_t)t * E_ + wid] = s;
}

__global__ void col_softmax_stats(const float* __restrict__ logits, float* __restrict__ zmax,
                                  float* __restrict__ zsum) {
    int be = blockIdx.x;
    int b = be / E_, e = be % E_;
    __shared__ float red[256];
    float mx = -3e38f;
    for (int s = threadIdx.x; s < S_; s += 256)
        mx = fmaxf(mx, logits[((size_t)b * S_ + s) * E_ + e]);
    red[threadIdx.x] = mx; __syncthreads();
    for (int s = 128; s > 0; s >>= 1) {
        if (threadIdx.x < s) red[threadIdx.x] = fmaxf(red[threadIdx.x], red[threadIdx.x + s]);
        __syncthreads();
    }
    mx = red[0]; __syncthreads();
    float sum = 0.f;
    for (int s = threadIdx.x; s < S_; s += 256)
        sum += expf(logits[((size_t)b * S_ + s) * E_ + e] - mx);
    red[threadIdx.x] = sum; __syncthreads();
    for (int s = 128; s > 0; s >>= 1) {
        if (threadIdx.x < s) red[threadIdx.x] += red[threadIdx.x + s];
        __syncthreads();
    }
    if (threadIdx.x == 0) { zmax[be] = mx; zsum[be] = red[0]; }
}

__global__ void top2_kernel(const float* __restrict__ logits, const float* __restrict__ zmax,
                            const float* __restrict__ zsum, int* __restrict__ cnt,
                            int* __restrict__ tok, int* __restrict__ sel,
                            int* __restrict__ pos, float* __restrict__ wgt) {
    int t = blockIdx.x * blockDim.x + threadIdx.x;
    if (t >= T_) return;
    int b = t / S_;
    float rw[E_];
#pragma unroll
    for (int e = 0; e < E_; e++)
        rw[e] = expf(logits[(size_t)t * E_ + e] - zmax[b * E_ + e]) / zsum[b * E_ + e];
    int e0 = 0; float v0 = rw[0];
#pragma unroll
    for (int e = 1; e < E_; e++) if (rw[e] > v0) { v0 = rw[e]; e0 = e; }
    int e1 = -1; float v1 = -3e38f;
#pragma unroll
    for (int e = 0; e < E_; e++) if (e != e0 && rw[e] > v1) { v1 = rw[e]; e1 = e; }
    float inv = 1.f / (v0 + v1);
    int p0 = atomicAdd(&cnt[e0], 1);
    tok[e0 * T_ + p0] = t;
    int p1 = atomicAdd(&cnt[e1], 1);
    tok[e1 * T_ + p1] = t;
    sel[2*t] = e0; pos[2*t] = p0; wgt[2*t] = v0 * inv;
    sel[2*t+1] = e1; pos[2*t+1] = p1; wgt[2*t+1] = v1 * inv;
}

__global__ void offsets_kernel(const int* __restrict__ cnt, int* __restrict__ off) {
    if (threadIdx.x == 0) {
        int s = 0;
        for (int e = 0; e < E_; e++) { off[e] = s; s += cnt[e]; }
    }
}

__global__ void gather_kernel(const float* __restrict__ expout, const int* __restrict__ off,
                              const int* __restrict__ sel, const int* __restrict__ pos,
                              const float* __restrict__ wgt, float* __restrict__ out) {
    int t = blockIdx.x;
    int e0 = sel[2*t], e1 = sel[2*t+1];
    size_t r0 = (size_t)(off[e0] + pos[2*t]) * D_;
    size_t r1 = (size_t)(off[e1] + pos[2*t+1]) * D_;
    float w0 = wgt[2*t], w1 = wgt[2*t+1];
    for (int i = threadIdx.x; i < D_; i += 256)
        out[(size_t)t * D_ + i] += w0 * expout[r0 + i] + w1 * expout[r1 + i];
}

// ---------------- host launch ----------------
extern "C" void kernel_launch(void* const* d_in, const int* in_sizes, int n_in,
                              void* d_out, int out_size) {
    const float* data   = (const float*)d_in[0];
    const float* mask   = (const float*)d_in[1];
    const float* ropec  = (const float*)d_in[2];
    const float* ropes  = (const float*)d_in[3];
    const float* anw    = (const float*)d_in[4];
    const float* fnw    = (const float*)d_in[5];
    const float* wq     = (const float*)d_in[6];
    const float* wk     = (const float*)d_in[7];
    const float* wv     = (const float*)d_in[8];
    const float* wo     = (const float*)d_in[9];
    const float* gate_w = (const float*)d_in[10];
    const float* w1     = (const float*)d_in[11];
    const float* w2     = (const float*)d_in[12];
    const float* w3     = (const float*)d_in[13];
    const float* w1_a   = (const float*)d_in[14];
    const float* w1_b   = (const float*)d_in[15];
    const float* w3_a   = (const float*)d_in[16];
    const float* w3_b   = (const float*)d_in[17];
    const float* w2_a   = (const float*)d_in[18];
    const float* w2_b   = (const float*)d_in[19];
    float* out = (float*)d_out;

    float *xn, *qb, *kb, *vb, *attn, *sn, *c1, *c3, *h1, *h3, *u1, *u3, *u2;
    float *logits, *zmax, *zsum, *wgt, *expout;
    int *cnt, *off, *tok, *sel, *pos;
    cudaGetSymbolAddress((void**)&xn, g_xn);
    cudaGetSymbolAddress((void**)&qb, g_q);
    cudaGetSymbolAddress((void**)&kb, g_k);
    cudaGetSymbolAddress((void**)&vb, g_v);
    cudaGetSymbolAddress((void**)&attn, g_attn);
    cudaGetSymbolAddress((void**)&sn, g_sn);
    cudaGetSymbolAddress((void**)&c1, g_c1);
    cudaGetSymbolAddress((void**)&c3, g_c3);
    cudaGetSymbolAddress((void**)&h1, g_h1);
    cudaGetSymbolAddress((void**)&h3, g_h3);
    cudaGetSymbolAddress((void**)&u1, g_u1);
    cudaGetSymbolAddress((void**)&u3, g_u3);
    cudaGetSymbolAddress((void**)&u2, g_u2);
    cudaGetSymbolAddress((void**)&expout, g_expout);
    cudaGetSymbolAddress((void**)&logits, g_logits);
    cudaGetSymbolAddress((void**)&zmax, g_zmax);
    cudaGetSymbolAddress((void**)&zsum, g_zsum);
    cudaGetSymbolAddress((void**)&cnt, g_cnt);
    cudaGetSymbolAddress((void**)&off, g_off);
    cudaGetSymbolAddress((void**)&tok, g_tok);
    cudaGetSymbolAddress((void**)&sel, g_sel);
    cudaGetSymbolAddress((void**)&pos, g_pos);
    cudaGetSymbolAddress((void**)&wgt, g_wgt);

    cudaFuncSetAttribute(attn_kernel, cudaFuncAttributeMaxDynamicSharedMemorySize, ATTN_SMEM);
    cudaFuncSetAttribute(gemm_mma, cudaFuncAttributeMaxDynamicSharedMemorySize, GEMM_SMEM);

    reset_kernel<<<1, 32>>>(cnt);
    rmsnorm_kernel<<<T_, 256>>>(data, anw, xn);

    // QKV projections (tf32 mma v2); rope fused into q/k epilogues
    gemm_mma<<<dim3(D_/256, T_/128, 1), 256, GEMM_SMEM>>>(xn, wq, qb, T_, D_, D_,
        nullptr, nullptr, nullptr, ropec, ropes);
    gemm_mma<<<dim3((HKV_*HD_)/256, T_/128, 1), 256, GEMM_SMEM>>>(xn, wk, kb, T_, HKV_*HD_, D_,
        nullptr, nullptr, nullptr, ropec, ropes);
    gemm_mma<<<dim3((HKV_*HD_)/256, T_/128, 1), 256, GEMM_SMEM>>>(xn, wv, vb, T_, HKV_*HD_, D_,
        nullptr, nullptr, nullptr, nullptr, nullptr);

    attn_kernel<<<dim3(S_/64, H_, B_), 256, ATTN_SMEM>>>(qb, kb, vb, mask, attn);

    // out = data + attn @ wo^T
    gemm_mma<<<dim3(D_/256, T_/128, 1), 256, GEMM_SMEM>>>(attn, wo, out, T_, D_, D_,
        data, nullptr, nullptr, nullptr, nullptr);

    rmsnorm_kernel<<<T_, 256>>>(out, fnw, sn);

    router_logits_kernel<<<T_, 256>>>(sn, gate_w, logits);
    col_softmax_stats<<<B_*E_, 256>>>(logits, zmax, zsum);
    top2_kernel<<<T_/256, 256>>>(logits, zmax, zsum, cnt, tok, sel, pos, wgt);
    offsets_kernel<<<1, 32>>>(cnt, off);

    // dense c1/c3 (tf32 mma v2)
    gemm_mma<<<dim3(F_/256, T_/128, 1), 256, GEMM_SMEM>>>(sn, w1, c1, T_, F_, D_,
        nullptr, nullptr, nullptr, nullptr, nullptr);
    gemm_mma<<<dim3(F_/256, T_/128, 1), 256, GEMM_SMEM>>>(sn, w3, c3, T_, F_, D_,
        nullptr, nullptr, nullptr, nullptr, nullptr);

    // ---- expert-batched LoRA path (z = expert) ----
    // h3 first, then h1 with fused silu(h1)*h3 -> sr (stored in h1)
    gemm_small<<<dim3(1, T_/64, E_), 256>>>(sn, w3_a, u3, R_, D_,
        tok, 1, nullptr, 1.f, 0, cnt, off, (size_t)R_*D_, nullptr);
    gemm_small<<<dim3(F_/64, T_/64, E_), 256>>>(u3, w3_b, h3, F_, R_,
        tok, 0, c3, SCALE_, 0, cnt, off, (size_t)F_*R_, nullptr);
    gemm_small<<<dim3(1, T_/64, E_), 256>>>(sn, w1_a, u1, R_, D_,
        tok, 1, nullptr, 1.f, 0, cnt, off, (size_t)R_*D_, nullptr);
    gemm_small<<<dim3(F_/64, T_/64, E_), 256>>>(u1, w1_b, h1, F_, R_,
        tok, 0, c1, SCALE_, 0, cnt, off, (size_t)F_*R_, h3);
    // u2 = sr @ w2_a^T
    gemm_small<<<dim3(1, T_/64, E_), 256>>>(h1, w2_a, u2, R_, F_,
        tok, 0, nullptr, 1.f, 0, cnt, off, (size_t)R_*F_, nullptr);
    // expout = sr @ w2^T  (tf32 mma v2, expert-batched with dynamic M)
    gemm_mma<<<dim3(D_/256, T_/128, E_), 256, GEMM_SMEM>>>(h1, w2, expout, T_, D_, F_,
        nullptr, cnt, off, nullptr, nullptr);
    // expout += SCALE * u2 @ w2_b^T
    gemm_small<<<dim3(D_/64, T_/64, E_), 256>>>(u2, w2_b, expout, D_, R_,
        tok, 0, nullptr, SCALE_, 1, cnt, off, (size_t)D_*R_, nullptr);

    // out[t] += w0*expout[slot0] + w1*expout[slot1]
    gather_kernel<<<T_, 256>>>(expout, off, sel, pos, wgt, out);
}